// round 2
// baseline (speedup 1.0000x reference)
#include <cuda_runtime.h>
#include <math.h>

#define BS 4
#define NN 2048
#define H 2
#define F_IN 768
#define F_OUT 768
#define NEG 0.2f
#define WPR 64   // mask words per row (NN/32)

// Scratch (device globals: allocation-free per harness rules)
__device__ float g_hprime[BS * H * NN * F_OUT];        // 50.3 MB
__device__ float g_src[BS * H * NN];
__device__ float g_dst[BS * H * NN];
__device__ float g_mx[BS * H * NN];
__device__ float g_inv[BS * H * NN];
__device__ unsigned int g_mask[BS * NN * WPR];         // 2 MB adjacency bitmask (diag included)
__device__ int g_is_i32;

// ---------------------------------------------------------------------------
// Kernel 0a: detect adjacency dtype. int32 0/1 values => first 64 words all <=1.
// uint8-packed random 0/1 bytes => words like 0x00010101 (P(word<=1) ~ 2^-24).
// ---------------------------------------------------------------------------
__global__ void detect_adj(const unsigned int* __restrict__ adj) {
    if (threadIdx.x == 0 && blockIdx.x == 0) {
        int ok = 1;
        for (int i = 0; i < 64; i++)
            if (adj[i] > 1u) ok = 0;
        g_is_i32 = ok;
    }
}

// ---------------------------------------------------------------------------
// Kernel 0b: pack adjacency (either dtype) into bitmask, OR in diagonal.
// One thread per 32-bit mask word. Total words = BS*NN*WPR = 524288.
// ---------------------------------------------------------------------------
__global__ __launch_bounds__(256) void pack_adj(const void* __restrict__ adjraw) {
    int idx = blockIdx.x * blockDim.x + threadIdx.x;
    if (idx >= BS * NN * WPR) return;
    int w = idx % WPR;
    int i = (idx / WPR) % NN;
    int b = idx / (WPR * NN);
    size_t base = ((size_t)b * NN + i) * NN + (size_t)w * 32;
    unsigned int bits = 0;
    if (g_is_i32) {
        const int* p = (const int*)adjraw + base;
#pragma unroll
        for (int t = 0; t < 32; t++) bits |= (unsigned)(p[t] != 0) << t;
    } else {
        const unsigned char* p = (const unsigned char*)adjraw + base;
#pragma unroll
        for (int t = 0; t < 32; t++) bits |= (unsigned)(p[t] != 0) << t;
    }
    if ((i >> 5) == w) bits |= 1u << (i & 31);  // diagonal
    g_mask[idx] = bits;
}

// ---------------------------------------------------------------------------
// Kernel 1: h_prime[bh] = h[b] @ w[head]   (M=2048, N=768, K=768)
// ---------------------------------------------------------------------------
__global__ __launch_bounds__(256) void hp_gemm(const float* __restrict__ hmat,
                                               const float* __restrict__ wmat) {
    int bh = blockIdx.z;
    int b = bh / H, hd = bh % H;
    int row0 = blockIdx.y * 128, col0 = blockIdx.x * 128;
    const float* A = hmat + (size_t)b * NN * F_IN;
    const float* Bm = wmat + (size_t)hd * F_IN * F_OUT;

    __shared__ __align__(16) float As[8][128];
    __shared__ __align__(16) float Bs[8][128];

    int tid = threadIdx.x;
    int ty = tid >> 4, tx = tid & 15;
    int ar = tid >> 1, ak = (tid & 1) * 4;
    int br = tid >> 5, bc = (tid & 31) * 4;

    float acc[8][8];
#pragma unroll
    for (int i = 0; i < 8; i++)
#pragma unroll
        for (int j = 0; j < 8; j++) acc[i][j] = 0.f;

    for (int k0 = 0; k0 < F_IN; k0 += 8) {
        float4 av = *(const float4*)&A[(size_t)(row0 + ar) * F_IN + k0 + ak];
        As[ak + 0][ar] = av.x; As[ak + 1][ar] = av.y;
        As[ak + 2][ar] = av.z; As[ak + 3][ar] = av.w;
        *(float4*)&Bs[br][bc] =
            *(const float4*)&Bm[(size_t)(k0 + br) * F_OUT + col0 + bc];
        __syncthreads();
#pragma unroll
        for (int k = 0; k < 8; k++) {
            float a[8], bb[8];
            *(float4*)&a[0]  = *(float4*)&As[k][ty * 8];
            *(float4*)&a[4]  = *(float4*)&As[k][ty * 8 + 4];
            *(float4*)&bb[0] = *(float4*)&Bs[k][tx * 8];
            *(float4*)&bb[4] = *(float4*)&Bs[k][tx * 8 + 4];
#pragma unroll
            for (int i = 0; i < 8; i++)
#pragma unroll
                for (int j = 0; j < 8; j++) acc[i][j] += a[i] * bb[j];
        }
        __syncthreads();
    }
    float* O = g_hprime + (size_t)bh * NN * F_OUT;
#pragma unroll
    for (int i = 0; i < 8; i++) {
        float4 v0 = make_float4(acc[i][0], acc[i][1], acc[i][2], acc[i][3]);
        float4 v1 = make_float4(acc[i][4], acc[i][5], acc[i][6], acc[i][7]);
        size_t base = (size_t)(row0 + ty * 8 + i) * F_OUT + col0 + tx * 8;
        *(float4*)&O[base]     = v0;
        *(float4*)&O[base + 4] = v1;
    }
}

// ---------------------------------------------------------------------------
// Kernel 2: per-row dots  src[row]=tanh(hp[row])·a_src[head], dst likewise.
// ---------------------------------------------------------------------------
__global__ __launch_bounds__(256) void row_dots(const float* __restrict__ a_src,
                                                const float* __restrict__ a_dst) {
    int row = blockIdx.x;
    int hd = (row / NN) % H;
    const float* hp = g_hprime + (size_t)row * F_OUT;
    const float* as = a_src + hd * F_OUT;
    const float* ad = a_dst + hd * F_OUT;
    int tid = threadIdx.x;
    float ps = 0.f, pd = 0.f;
    for (int f = tid; f < F_OUT; f += 256) {
        float t = tanhf(hp[f]);
        ps += t * as[f];
        pd += t * ad[f];
    }
    __shared__ float r1[8], r2[8];
    for (int o = 16; o; o >>= 1) {
        ps += __shfl_down_sync(0xffffffffu, ps, o);
        pd += __shfl_down_sync(0xffffffffu, pd, o);
    }
    if ((tid & 31) == 0) { r1[tid >> 5] = ps; r2[tid >> 5] = pd; }
    __syncthreads();
    if (tid == 0) {
        float a = 0.f, bsum = 0.f;
        for (int t = 0; t < 8; t++) { a += r1[t]; bsum += r2[t]; }
        g_src[row] = a;
        g_dst[row] = bsum;
    }
}

// ---------------------------------------------------------------------------
// Kernel 3: softmax row stats — max and 1/sumexp over masked leaky scores.
// ---------------------------------------------------------------------------
__global__ __launch_bounds__(256) void row_stats() {
    int row = blockIdx.x;
    int i = row % NN;
    int bh = row / NN;
    int b = bh / H;
    const unsigned int* mrow = g_mask + ((size_t)b * NN + i) * WPR;
    const float* dv = g_dst + (size_t)bh * NN;
    float si = g_src[row];
    int tid = threadIdx.x;

    float mx = -INFINITY;
    for (int j = tid; j < NN; j += 256) {
        if ((mrow[j >> 5] >> (j & 31)) & 1u) {
            float s = si + dv[j];
            s = (s >= 0.f) ? s : NEG * s;
            mx = fmaxf(mx, s);
        }
    }
    __shared__ float red[8];
    for (int o = 16; o; o >>= 1) mx = fmaxf(mx, __shfl_down_sync(0xffffffffu, mx, o));
    if ((tid & 31) == 0) red[tid >> 5] = mx;
    __syncthreads();
    if (tid == 0) {
        float m = red[0];
        for (int t = 1; t < 8; t++) m = fmaxf(m, red[t]);
        red[0] = m;
    }
    __syncthreads();
    mx = red[0];
    __syncthreads();

    float sum = 0.f;
    for (int j = tid; j < NN; j += 256) {
        if ((mrow[j >> 5] >> (j & 31)) & 1u) {
            float s = si + dv[j];
            s = (s >= 0.f) ? s : NEG * s;
            sum += __expf(s - mx);
        }
    }
    for (int o = 16; o; o >>= 1) sum += __shfl_down_sync(0xffffffffu, sum, o);
    if ((tid & 31) == 0) red[tid >> 5] = sum;
    __syncthreads();
    if (tid == 0) {
        float t0 = 0.f;
        for (int t = 0; t < 8; t++) t0 += red[t];
        g_mx[row] = mx;
        g_inv[row] = 1.f / t0;
    }
}

// ---------------------------------------------------------------------------
// Kernel 4: out[bh] = P[bh] @ h_prime[bh] + bias.  (M=2048, N=768, K=2048)
// P tile generated on the fly from src/dst/bitmask + row stats.
// ---------------------------------------------------------------------------
__global__ __launch_bounds__(256) void attn_gemm(float* __restrict__ out,
                                                 const float* __restrict__ bias) {
    int bh = blockIdx.z;
    int b = bh / H;
    int row0 = blockIdx.y * 128, col0 = blockIdx.x * 128;
    const float* Bm = g_hprime + (size_t)bh * NN * F_OUT;
    const float* dv = g_dst + (size_t)bh * NN;

    __shared__ __align__(16) float As[8][128];
    __shared__ __align__(16) float Bs[8][128];
    __shared__ float s_src[128], s_mx[128], s_inv[128];

    int tid = threadIdx.x;
    if (tid < 128) {
        int r = bh * NN + row0 + tid;
        s_src[tid] = g_src[r];
        s_mx[tid]  = g_mx[r];
        s_inv[tid] = g_inv[r];
    }
    __syncthreads();

    int ty = tid >> 4, tx = tid & 15;
    int arr = tid >> 1, ak = (tid & 1) * 4;
    int br = tid >> 5, bc = (tid & 31) * 4;
    int gi = row0 + arr;
    const unsigned int* mrow = g_mask + ((size_t)b * NN + gi) * WPR;
    float srcv = s_src[arr], mxv = s_mx[arr], invv = s_inv[arr];

    float acc[8][8];
#pragma unroll
    for (int i = 0; i < 8; i++)
#pragma unroll
        for (int j = 0; j < 8; j++) acc[i][j] = 0.f;

    for (int k0 = 0; k0 < NN; k0 += 8) {
        int jb = k0 + ak;                       // 4-aligned, within one mask word
        unsigned int bits = mrow[jb >> 5] >> (jb & 31);
#pragma unroll
        for (int q = 0; q < 4; q++) {
            int j = jb + q;
            float s = srcv + dv[j];
            s = (s >= 0.f) ? s : NEG * s;
            As[ak + q][arr] = ((bits >> q) & 1u) ? __expf(s - mxv) * invv : 0.f;
        }
        *(float4*)&Bs[br][bc] =
            *(const float4*)&Bm[(size_t)(k0 + br) * F_OUT + col0 + bc];
        __syncthreads();
#pragma unroll
        for (int k = 0; k < 8; k++) {
            float a[8], bb[8];
            *(float4*)&a[0]  = *(float4*)&As[k][ty * 8];
            *(float4*)&a[4]  = *(float4*)&As[k][ty * 8 + 4];
            *(float4*)&bb[0] = *(float4*)&Bs[k][tx * 8];
            *(float4*)&bb[4] = *(float4*)&Bs[k][tx * 8 + 4];
#pragma unroll
            for (int i = 0; i < 8; i++)
#pragma unroll
                for (int j = 0; j < 8; j++) acc[i][j] += a[i] * bb[j];
        }
        __syncthreads();
    }

#pragma unroll
    for (int i = 0; i < 8; i++) {
        size_t base = ((size_t)bh * NN + row0 + ty * 8 + i) * F_OUT + col0 + tx * 8;
        float4 v0 = make_float4(acc[i][0] + bias[col0 + tx * 8 + 0],
                                acc[i][1] + bias[col0 + tx * 8 + 1],
                                acc[i][2] + bias[col0 + tx * 8 + 2],
                                acc[i][3] + bias[col0 + tx * 8 + 3]);
        float4 v1 = make_float4(acc[i][4] + bias[col0 + tx * 8 + 4],
                                acc[i][5] + bias[col0 + tx * 8 + 5],
                                acc[i][6] + bias[col0 + tx * 8 + 6],
                                acc[i][7] + bias[col0 + tx * 8 + 7]);
        *(float4*)&out[base]     = v0;
        *(float4*)&out[base + 4] = v1;
    }
}

// ---------------------------------------------------------------------------
extern "C" void kernel_launch(void* const* d_in, const int* in_sizes, int n_in,
                              void* d_out, int out_size) {
    // Identify inputs by element count (robust to metadata ordering).
    const float* hmat = 0; const void* adj = 0; const float* wmat = 0;
    const float* a_src = 0; const float* a_dst = 0; const float* bias = 0;
    for (int i = 0; i < n_in; i++) {
        long sz = in_sizes[i];
        if (sz == (long)BS * NN * F_IN)      hmat = (const float*)d_in[i];
        else if (sz == (long)BS * NN * NN)   adj  = d_in[i];
        else if (sz == (long)H * F_IN * F_OUT) wmat = (const float*)d_in[i];
        else if (sz == (long)H * F_OUT) {
            if (!a_src) a_src = (const float*)d_in[i];
            else        a_dst = (const float*)d_in[i];
        }
        else if (sz == (long)F_OUT)          bias = (const float*)d_in[i];
    }
    float* out = (float*)d_out;

    detect_adj<<<1, 32>>>((const unsigned int*)adj);
    pack_adj<<<(BS * NN * WPR + 255) / 256, 256>>>(adj);

    dim3 gGemm(F_OUT / 128, NN / 128, BS * H);  // (6, 16, 8)
    hp_gemm<<<gGemm, 256>>>(hmat, wmat);
    row_dots<<<BS * H * NN, 256>>>(a_src, a_dst);
    row_stats<<<BS * H * NN, 256>>>();
    attn_gemm<<<gGemm, 256>>>(out, bias);
}

// round 3
// speedup vs baseline: 1.4039x; 1.4039x over previous
#include <cuda_runtime.h>
#include <math.h>

#define BS 4
#define NN 2048
#define H 2
#define F_IN 768
#define F_OUT 768
#define NEG 0.2f
#define WPR 64         // mask words per row (NN/32)
#define AS_STRIDE 20   // A smem stride (BK=16 + 4 pad): conflict-free frag loads
#define BS_STRIDE 136  // B smem stride (BN=128 + 8 pad): conflict-free frag loads

// Scratch (device globals: allocation-free per harness rules)
__device__ float g_hprime[BS * H * NN * F_OUT];        // 50.3 MB
__device__ float g_src[BS * H * NN];
__device__ float g_dst[BS * H * NN];
__device__ float g_mx[BS * H * NN];
__device__ float g_inv[BS * H * NN];
__device__ unsigned int g_mask[BS * NN * WPR];         // 2 MB bitmask (diag OR'd in)
__device__ int g_is_i32;

// ---------------------------------------------------------------------------
// tf32 helpers
// ---------------------------------------------------------------------------
__device__ __forceinline__ unsigned f2tf(float x) {
    unsigned r;
    asm("cvt.rna.tf32.f32 %0, %1;" : "=r"(r) : "f"(x));
    return r;
}
// split a into hi (tf32) + lo (tf32 of residual)
__device__ __forceinline__ void f2tf_split(float x, unsigned& hi, unsigned& lo) {
    hi = f2tf(x);
    lo = f2tf(x - __uint_as_float(hi));
}
__device__ __forceinline__ void mma_tf32(float* d, const unsigned* a, const unsigned* b) {
    asm volatile(
        "mma.sync.aligned.m16n8k8.row.col.f32.tf32.tf32.f32 "
        "{%0,%1,%2,%3}, {%4,%5,%6,%7}, {%8,%9}, {%0,%1,%2,%3};"
        : "+f"(d[0]), "+f"(d[1]), "+f"(d[2]), "+f"(d[3])
        : "r"(a[0]), "r"(a[1]), "r"(a[2]), "r"(a[3]), "r"(b[0]), "r"(b[1]));
}

// ---------------------------------------------------------------------------
// Kernel 0a: detect adjacency dtype (int32 0/1 vs packed bytes)
// ---------------------------------------------------------------------------
__global__ void detect_adj(const unsigned int* __restrict__ adj) {
    if (threadIdx.x == 0 && blockIdx.x == 0) {
        int ok = 1;
        for (int i = 0; i < 64; i++)
            if (adj[i] > 1u) ok = 0;
        g_is_i32 = ok;
    }
}

// ---------------------------------------------------------------------------
// Kernel 0b: pack adjacency into bitmask, OR in diagonal.
// ---------------------------------------------------------------------------
__global__ __launch_bounds__(256) void pack_adj(const void* __restrict__ adjraw) {
    int idx = blockIdx.x * blockDim.x + threadIdx.x;
    if (idx >= BS * NN * WPR) return;
    int w = idx % WPR;
    int i = (idx / WPR) % NN;
    int b = idx / (WPR * NN);
    size_t base = ((size_t)b * NN + i) * NN + (size_t)w * 32;
    unsigned int bits = 0;
    if (g_is_i32) {
        const int* p = (const int*)adjraw + base;
#pragma unroll
        for (int t = 0; t < 32; t++) bits |= (unsigned)(p[t] != 0) << t;
    } else {
        const unsigned char* p = (const unsigned char*)adjraw + base;
#pragma unroll
        for (int t = 0; t < 32; t++) bits |= (unsigned)(p[t] != 0) << t;
    }
    if ((i >> 5) == w) bits |= 1u << (i & 31);
    g_mask[idx] = bits;
}

// ---------------------------------------------------------------------------
// Kernel 1: h_prime[bh] = h[b] @ w[head]  via 3xTF32 (fp32-accurate).
// 128x128 block, BK=16, 256 threads = 8 warps (2m x 4n), warp tile 64x32.
// ---------------------------------------------------------------------------
__global__ __launch_bounds__(256) void hp_gemm_tc(const float* __restrict__ hmat,
                                                  const float* __restrict__ wmat) {
    __shared__ unsigned Ahi[128 * AS_STRIDE], Alo[128 * AS_STRIDE];
    __shared__ unsigned Bhi[16 * BS_STRIDE], Blo[16 * BS_STRIDE];

    int bh = blockIdx.z, b = bh / H, hd = bh % H;
    int row0 = blockIdx.y * 128, col0 = blockIdx.x * 128;
    const float* A = hmat + (size_t)b * NN * F_IN + (size_t)row0 * F_IN;
    const float* Bm = wmat + (size_t)hd * F_IN * F_OUT + col0;

    int tid = threadIdx.x, lane = tid & 31, warp = tid >> 5;
    int wm = (warp & 1) * 64, wn = (warp >> 1) * 32;

    float acc[4][4][4];
#pragma unroll
    for (int mi = 0; mi < 4; mi++)
#pragma unroll
        for (int ni = 0; ni < 4; ni++)
#pragma unroll
            for (int r = 0; r < 4; r++) acc[mi][ni][r] = 0.f;

    int ar = tid >> 1, ac = (tid & 1) * 8;       // A: 2 thr/row, 8 floats each
    int kr = tid >> 4, nc = (tid & 15) * 8;      // B: 16 thr/row, 8 floats each

    for (int k0 = 0; k0 < F_IN; k0 += 16) {
#pragma unroll
        for (int u = 0; u < 2; u++) {
            float4 v = *(const float4*)&A[(size_t)ar * F_IN + k0 + ac + u * 4];
            int o = ar * AS_STRIDE + ac + u * 4;
            f2tf_split(v.x, Ahi[o + 0], Alo[o + 0]);
            f2tf_split(v.y, Ahi[o + 1], Alo[o + 1]);
            f2tf_split(v.z, Ahi[o + 2], Alo[o + 2]);
            f2tf_split(v.w, Ahi[o + 3], Alo[o + 3]);
        }
#pragma unroll
        for (int u = 0; u < 2; u++) {
            float4 v = *(const float4*)&Bm[(size_t)(k0 + kr) * F_OUT + nc + u * 4];
            int o = kr * BS_STRIDE + nc + u * 4;
            f2tf_split(v.x, Bhi[o + 0], Blo[o + 0]);
            f2tf_split(v.y, Bhi[o + 1], Blo[o + 1]);
            f2tf_split(v.z, Bhi[o + 2], Blo[o + 2]);
            f2tf_split(v.w, Bhi[o + 3], Blo[o + 3]);
        }
        __syncthreads();
#pragma unroll
        for (int kk = 0; kk < 16; kk += 8) {
            unsigned ah[4][4], al[4][4], bh_[4][2], bl_[4][2];
#pragma unroll
            for (int mi = 0; mi < 4; mi++) {
                int r = wm + mi * 16 + (lane >> 2);
                int c = kk + (lane & 3);
                ah[mi][0] = Ahi[r * AS_STRIDE + c];
                ah[mi][1] = Ahi[(r + 8) * AS_STRIDE + c];
                ah[mi][2] = Ahi[r * AS_STRIDE + c + 4];
                ah[mi][3] = Ahi[(r + 8) * AS_STRIDE + c + 4];
                al[mi][0] = Alo[r * AS_STRIDE + c];
                al[mi][1] = Alo[(r + 8) * AS_STRIDE + c];
                al[mi][2] = Alo[r * AS_STRIDE + c + 4];
                al[mi][3] = Alo[(r + 8) * AS_STRIDE + c + 4];
            }
#pragma unroll
            for (int ni = 0; ni < 4; ni++) {
                int n = wn + ni * 8 + (lane >> 2);
                int k = kk + (lane & 3);
                bh_[ni][0] = Bhi[k * BS_STRIDE + n];
                bh_[ni][1] = Bhi[(k + 4) * BS_STRIDE + n];
                bl_[ni][0] = Blo[k * BS_STRIDE + n];
                bl_[ni][1] = Blo[(k + 4) * BS_STRIDE + n];
            }
#pragma unroll
            for (int mi = 0; mi < 4; mi++)
#pragma unroll
                for (int ni = 0; ni < 4; ni++) {
                    mma_tf32(acc[mi][ni], ah[mi], bh_[ni]);
                    mma_tf32(acc[mi][ni], ah[mi], bl_[ni]);
                    mma_tf32(acc[mi][ni], al[mi], bh_[ni]);
                }
        }
        __syncthreads();
    }

    float* O = g_hprime + (size_t)bh * NN * F_OUT;
#pragma unroll
    for (int mi = 0; mi < 4; mi++)
#pragma unroll
        for (int ni = 0; ni < 4; ni++) {
            int r = row0 + wm + mi * 16 + (lane >> 2);
            int c = col0 + wn + ni * 8 + 2 * (lane & 3);
            O[(size_t)r * F_OUT + c]           = acc[mi][ni][0];
            O[(size_t)r * F_OUT + c + 1]       = acc[mi][ni][1];
            O[(size_t)(r + 8) * F_OUT + c]     = acc[mi][ni][2];
            O[(size_t)(r + 8) * F_OUT + c + 1] = acc[mi][ni][3];
        }
}

// ---------------------------------------------------------------------------
// Kernel 2: per-row dots  src[row]=tanh(hp[row])·a_src[head], dst likewise.
// ---------------------------------------------------------------------------
__global__ __launch_bounds__(256) void row_dots(const float* __restrict__ a_src,
                                                const float* __restrict__ a_dst) {
    int row = blockIdx.x;
    int hd = (row / NN) % H;
    const float* hp = g_hprime + (size_t)row * F_OUT;
    const float* as = a_src + hd * F_OUT;
    const float* ad = a_dst + hd * F_OUT;
    int tid = threadIdx.x;
    float ps = 0.f, pd = 0.f;
    for (int f = tid; f < F_OUT; f += 256) {
        float t = tanhf(hp[f]);
        ps += t * as[f];
        pd += t * ad[f];
    }
    __shared__ float r1[8], r2[8];
    for (int o = 16; o; o >>= 1) {
        ps += __shfl_down_sync(0xffffffffu, ps, o);
        pd += __shfl_down_sync(0xffffffffu, pd, o);
    }
    if ((tid & 31) == 0) { r1[tid >> 5] = ps; r2[tid >> 5] = pd; }
    __syncthreads();
    if (tid == 0) {
        float a = 0.f, bsum = 0.f;
        for (int t = 0; t < 8; t++) { a += r1[t]; bsum += r2[t]; }
        g_src[row] = a;
        g_dst[row] = bsum;
    }
}

// ---------------------------------------------------------------------------
// Kernel 3: softmax row stats — max and 1/sumexp over masked leaky scores.
// ---------------------------------------------------------------------------
__global__ __launch_bounds__(256) void row_stats() {
    int row = blockIdx.x;
    int i = row % NN;
    int bh = row / NN;
    int b = bh / H;
    const unsigned int* mrow = g_mask + ((size_t)b * NN + i) * WPR;
    const float* dv = g_dst + (size_t)bh * NN;
    float si = g_src[row];
    int tid = threadIdx.x;

    float mx = -INFINITY;
    for (int j = tid; j < NN; j += 256) {
        if ((mrow[j >> 5] >> (j & 31)) & 1u) {
            float s = si + dv[j];
            s = (s >= 0.f) ? s : NEG * s;
            mx = fmaxf(mx, s);
        }
    }
    __shared__ float red[8];
    for (int o = 16; o; o >>= 1) mx = fmaxf(mx, __shfl_down_sync(0xffffffffu, mx, o));
    if ((tid & 31) == 0) red[tid >> 5] = mx;
    __syncthreads();
    if (tid == 0) {
        float m = red[0];
        for (int t = 1; t < 8; t++) m = fmaxf(m, red[t]);
        red[0] = m;
    }
    __syncthreads();
    mx = red[0];
    __syncthreads();

    float sum = 0.f;
    for (int j = tid; j < NN; j += 256) {
        if ((mrow[j >> 5] >> (j & 31)) & 1u) {
            float s = si + dv[j];
            s = (s >= 0.f) ? s : NEG * s;
            sum += __expf(s - mx);
        }
    }
    for (int o = 16; o; o >>= 1) sum += __shfl_down_sync(0xffffffffu, sum, o);
    if ((tid & 31) == 0) red[tid >> 5] = sum;
    __syncthreads();
    if (tid == 0) {
        float t0 = 0.f;
        for (int t = 0; t < 8; t++) t0 += red[t];
        g_mx[row] = mx;
        g_inv[row] = 1.f / t0;
    }
}

// ---------------------------------------------------------------------------
// Kernel 4: out = P @ h_prime + bias, single tf32. P generated on the fly.
// 128x128 block, BK=16, 256 threads = 8 warps (2m x 4n).
// ---------------------------------------------------------------------------
__global__ __launch_bounds__(256) void attn_gemm_tc(float* __restrict__ out,
                                                    const float* __restrict__ bias) {
    __shared__ unsigned Asm[128 * AS_STRIDE];
    __shared__ unsigned Bsm[16 * BS_STRIDE];
    __shared__ float s_src[128], s_mx[128], s_inv[128];

    int bh = blockIdx.z, b = bh / H;
    int row0 = blockIdx.y * 128, col0 = blockIdx.x * 128;
    const float* Bm = g_hprime + (size_t)bh * NN * F_OUT + col0;
    const float* dv = g_dst + (size_t)bh * NN;
    const unsigned int* mbase = g_mask + ((size_t)b * NN + row0) * WPR;

    int tid = threadIdx.x, lane = tid & 31, warp = tid >> 5;
    if (tid < 128) {
        int r = bh * NN + row0 + tid;
        s_src[tid] = g_src[r];
        s_mx[tid]  = g_mx[r];
        s_inv[tid] = g_inv[r];
    }
    __syncthreads();

    int wm = (warp & 1) * 64, wn = (warp >> 1) * 32;

    float acc[4][4][4];
#pragma unroll
    for (int mi = 0; mi < 4; mi++)
#pragma unroll
        for (int ni = 0; ni < 4; ni++)
#pragma unroll
            for (int r = 0; r < 4; r++) acc[mi][ni][r] = 0.f;

    int jl = tid & 15, i0 = (tid >> 4) * 8;      // P gen: 16 j-lanes x 16 i-groups
    int kr = tid >> 4, nc = (tid & 15) * 8;      // B load

    for (int k0 = 0; k0 < NN; k0 += 16) {
        // Generate P tile column-chunk [128 x 16]
        int jg = k0 + jl;
        float dj = dv[jg];
        int wIdx = jg >> 5, bit = jg & 31;
#pragma unroll
        for (int r = 0; r < 8; r++) {
            int i = i0 + r;
            unsigned mword = mbase[i * WPR + wIdx];
            float s = s_src[i] + dj;
            s = (s >= 0.f) ? s : NEG * s;
            float p = ((mword >> bit) & 1u) ? __expf(s - s_mx[i]) * s_inv[i] : 0.f;
            Asm[i * AS_STRIDE + jl] = f2tf(p);
        }
        // B tile [16 x 128] from h_prime
#pragma unroll
        for (int u = 0; u < 2; u++) {
            float4 v = *(const float4*)&Bm[(size_t)(k0 + kr) * F_OUT + nc + u * 4];
            int o = kr * BS_STRIDE + nc + u * 4;
            Bsm[o + 0] = f2tf(v.x);
            Bsm[o + 1] = f2tf(v.y);
            Bsm[o + 2] = f2tf(v.z);
            Bsm[o + 3] = f2tf(v.w);
        }
        __syncthreads();
#pragma unroll
        for (int kk = 0; kk < 16; kk += 8) {
            unsigned af[4][4], bf[4][2];
#pragma unroll
            for (int mi = 0; mi < 4; mi++) {
                int r = wm + mi * 16 + (lane >> 2);
                int c = kk + (lane & 3);
                af[mi][0] = Asm[r * AS_STRIDE + c];
                af[mi][1] = Asm[(r + 8) * AS_STRIDE + c];
                af[mi][2] = Asm[r * AS_STRIDE + c + 4];
                af[mi][3] = Asm[(r + 8) * AS_STRIDE + c + 4];
            }
#pragma unroll
            for (int ni = 0; ni < 4; ni++) {
                int n = wn + ni * 8 + (lane >> 2);
                int k = kk + (lane & 3);
                bf[ni][0] = Bsm[k * BS_STRIDE + n];
                bf[ni][1] = Bsm[(k + 4) * BS_STRIDE + n];
            }
#pragma unroll
            for (int mi = 0; mi < 4; mi++)
#pragma unroll
                for (int ni = 0; ni < 4; ni++)
                    mma_tf32(acc[mi][ni], af[mi], bf[ni]);
        }
        __syncthreads();
    }

#pragma unroll
    for (int mi = 0; mi < 4; mi++)
#pragma unroll
        for (int ni = 0; ni < 4; ni++) {
            int r = row0 + wm + mi * 16 + (lane >> 2);
            int c = col0 + wn + ni * 8 + 2 * (lane & 3);
            float b0 = bias[c], b1 = bias[c + 1];
            size_t base0 = ((size_t)bh * NN + r) * F_OUT + c;
            size_t base1 = ((size_t)bh * NN + r + 8) * F_OUT + c;
            out[base0]     = acc[mi][ni][0] + b0;
            out[base0 + 1] = acc[mi][ni][1] + b1;
            out[base1]     = acc[mi][ni][2] + b0;
            out[base1 + 1] = acc[mi][ni][3] + b1;
        }
}

// ---------------------------------------------------------------------------
extern "C" void kernel_launch(void* const* d_in, const int* in_sizes, int n_in,
                              void* d_out, int out_size) {
    const float* hmat = 0; const void* adj = 0; const float* wmat = 0;
    const float* a_src = 0; const float* a_dst = 0; const float* bias = 0;
    for (int i = 0; i < n_in; i++) {
        long sz = in_sizes[i];
        if (sz == (long)BS * NN * F_IN)      hmat = (const float*)d_in[i];
        else if (sz == (long)BS * NN * NN)   adj  = d_in[i];
        else if (sz == (long)H * F_IN * F_OUT) wmat = (const float*)d_in[i];
        else if (sz == (long)H * F_OUT) {
            if (!a_src) a_src = (const float*)d_in[i];
            else        a_dst = (const float*)d_in[i];
        }
        else if (sz == (long)F_OUT)          bias = (const float*)d_in[i];
    }
    float* out = (float*)d_out;

    detect_adj<<<1, 32>>>((const unsigned int*)adj);
    pack_adj<<<(BS * NN * WPR + 255) / 256, 256>>>(adj);

    dim3 gGemm(F_OUT / 128, NN / 128, BS * H);  // (6, 16, 8)
    hp_gemm_tc<<<gGemm, 256>>>(hmat, wmat);
    row_dots<<<BS * H * NN, 256>>>(a_src, a_dst);
    row_stats<<<BS * H * NN, 256>>>();
    attn_gemm_tc<<<gGemm, 256>>>(out, bias);
}

// round 4
// speedup vs baseline: 1.6670x; 1.1874x over previous
#include <cuda_runtime.h>
#include <math.h>

#define BS 4
#define NN 2048
#define H 2
#define F_IN 768
#define F_OUT 768
#define WPR 64          // mask words per row (NN/32)
#define ASTR 20         // A smem row stride (16 + 4 pad) - conflict-free frag loads
#define BSTR 136        // B smem row stride (128 + 8 pad) - conflict-free frag loads

// ------------------------- device scratch (no allocs) ----------------------
__device__ float    g_hprime[BS * H * NN * F_OUT];    // fp32, for row_dots
__device__ unsigned g_hprime_t[BS * H * NN * F_OUT];  // tf32, attn B operand
__device__ unsigned g_h_hi[BS * NN * F_IN], g_h_lo[BS * NN * F_IN];
__device__ unsigned g_w_hi[H * F_IN * F_OUT], g_w_lo[H * F_IN * F_OUT];
__device__ float g_E[BS * H * NN];    // exp(src)
__device__ float g_G[BS * H * NN];    // exp(0.2 src)
__device__ float g_T[BS * H * NN];    // exp(-src)  (branch threshold)
__device__ float g_F[BS * H * NN];    // exp(dst)
__device__ float g_Hv[BS * H * NN];   // exp(0.2 dst)
__device__ float g_Es[BS * H * NN];   // E * inv_rowsum
__device__ float g_Gs[BS * H * NN];   // G * inv_rowsum
__device__ unsigned g_mask[BS * NN * WPR];
__device__ int g_is_i32;

// ------------------------------- helpers ------------------------------------
__device__ __forceinline__ unsigned f2tf(float x) {
    unsigned r;
    asm("cvt.rna.tf32.f32 %0, %1;" : "=r"(r) : "f"(x));
    return r;
}
__device__ __forceinline__ void mma_tf32(float* d, const unsigned* a, const unsigned* b) {
    asm volatile(
        "mma.sync.aligned.m16n8k8.row.col.f32.tf32.tf32.f32 "
        "{%0,%1,%2,%3}, {%4,%5,%6,%7}, {%8,%9}, {%0,%1,%2,%3};"
        : "+f"(d[0]), "+f"(d[1]), "+f"(d[2]), "+f"(d[3])
        : "r"(a[0]), "r"(a[1]), "r"(a[2]), "r"(a[3]), "r"(b[0]), "r"(b[1]));
}

// ------------------- kernel 0a: adjacency dtype detect ----------------------
__global__ void detect_adj(const unsigned int* __restrict__ adj) {
    if (threadIdx.x == 0 && blockIdx.x == 0) {
        int ok = 1;
        for (int i = 0; i < 64; i++)
            if (adj[i] > 1u) ok = 0;
        g_is_i32 = ok;
    }
}

// ------------------- kernel 0b: pack adjacency to bitmask -------------------
__global__ __launch_bounds__(256) void pack_adj(const void* __restrict__ adjraw) {
    int idx = blockIdx.x * blockDim.x + threadIdx.x;
    if (idx >= BS * NN * WPR) return;
    int w = idx % WPR;
    int i = (idx / WPR) % NN;
    size_t base = (size_t)(idx / WPR) * NN + (size_t)w * 32;
    unsigned bits = 0;
    if (g_is_i32) {
        const uint4* p = (const uint4*)((const unsigned*)adjraw + base);
#pragma unroll
        for (int q = 0; q < 8; q++) {
            uint4 v = p[q];
            bits |= (unsigned)(v.x != 0) << (4 * q);
            bits |= (unsigned)(v.y != 0) << (4 * q + 1);
            bits |= (unsigned)(v.z != 0) << (4 * q + 2);
            bits |= (unsigned)(v.w != 0) << (4 * q + 3);
        }
    } else {
        const unsigned char* p = (const unsigned char*)adjraw + base;
#pragma unroll
        for (int t = 0; t < 32; t++) bits |= (unsigned)(p[t] != 0) << t;
    }
    if ((i >> 5) == w) bits |= 1u << (i & 31);
    g_mask[idx] = bits;
}

// ------------------- kernel 0c: fp32 -> (tf32 hi, tf32 lo) ------------------
__global__ __launch_bounds__(256) void split_f32(const float4* __restrict__ src,
                                                 uint4* __restrict__ hi,
                                                 uint4* __restrict__ lo, int n4) {
    int i = blockIdx.x * blockDim.x + threadIdx.x;
    if (i >= n4) return;
    float4 v = src[i];
    uint4 h, l;
    h.x = f2tf(v.x); l.x = f2tf(v.x - __uint_as_float(h.x));
    h.y = f2tf(v.y); l.y = f2tf(v.y - __uint_as_float(h.y));
    h.z = f2tf(v.z); l.z = f2tf(v.z - __uint_as_float(h.z));
    h.w = f2tf(v.w); l.w = f2tf(v.w - __uint_as_float(h.w));
    hi[i] = h;
    lo[i] = l;
}

// ------------------- kernel 1: h_prime = h @ w  (3xTF32) --------------------
// 128x128 CTA, 256 thr = 8 warps (2m x 4n), warp tile 64x32, BK=16.
__global__ __launch_bounds__(256) void hp_gemm_tc() {
    __shared__ unsigned Ahi[128 * ASTR], Alo[128 * ASTR];
    __shared__ unsigned Bhi[16 * BSTR], Blo[16 * BSTR];

    int bh = blockIdx.z, b = bh / H, hd = bh % H;
    int row0 = blockIdx.y * 128, col0 = blockIdx.x * 128;
    const unsigned* Ah = g_h_hi + (size_t)b * NN * F_IN + (size_t)row0 * F_IN;
    const unsigned* Al = g_h_lo + (size_t)b * NN * F_IN + (size_t)row0 * F_IN;
    const unsigned* Bh = g_w_hi + (size_t)hd * F_IN * F_OUT + col0;
    const unsigned* Bl = g_w_lo + (size_t)hd * F_IN * F_OUT + col0;

    int tid = threadIdx.x, lane = tid & 31, warp = tid >> 5;
    int wm = (warp & 1) * 64, wn = (warp >> 1) * 32;

    float acc[4][4][4];
#pragma unroll
    for (int mi = 0; mi < 4; mi++)
#pragma unroll
        for (int ni = 0; ni < 4; ni++)
#pragma unroll
            for (int r = 0; r < 4; r++) acc[mi][ni][r] = 0.f;

    int ar = tid >> 1, ac = (tid & 1) * 8;
    int kr = tid >> 4, nc = (tid & 15) * 8;

    for (int k0 = 0; k0 < F_IN; k0 += 16) {
        *(uint4*)&Ahi[ar * ASTR + ac]     = *(const uint4*)&Ah[(size_t)ar * F_IN + k0 + ac];
        *(uint4*)&Ahi[ar * ASTR + ac + 4] = *(const uint4*)&Ah[(size_t)ar * F_IN + k0 + ac + 4];
        *(uint4*)&Alo[ar * ASTR + ac]     = *(const uint4*)&Al[(size_t)ar * F_IN + k0 + ac];
        *(uint4*)&Alo[ar * ASTR + ac + 4] = *(const uint4*)&Al[(size_t)ar * F_IN + k0 + ac + 4];
        *(uint4*)&Bhi[kr * BSTR + nc]     = *(const uint4*)&Bh[(size_t)(k0 + kr) * F_OUT + nc];
        *(uint4*)&Bhi[kr * BSTR + nc + 4] = *(const uint4*)&Bh[(size_t)(k0 + kr) * F_OUT + nc + 4];
        *(uint4*)&Blo[kr * BSTR + nc]     = *(const uint4*)&Bl[(size_t)(k0 + kr) * F_OUT + nc];
        *(uint4*)&Blo[kr * BSTR + nc + 4] = *(const uint4*)&Bl[(size_t)(k0 + kr) * F_OUT + nc + 4];
        __syncthreads();
#pragma unroll
        for (int kk = 0; kk < 16; kk += 8) {
            unsigned ah[4][4], al[4][4], bhf[4][2], blf[4][2];
#pragma unroll
            for (int mi = 0; mi < 4; mi++) {
                int r = wm + mi * 16 + (lane >> 2);
                int c = kk + (lane & 3);
                ah[mi][0] = Ahi[r * ASTR + c];
                ah[mi][1] = Ahi[(r + 8) * ASTR + c];
                ah[mi][2] = Ahi[r * ASTR + c + 4];
                ah[mi][3] = Ahi[(r + 8) * ASTR + c + 4];
                al[mi][0] = Alo[r * ASTR + c];
                al[mi][1] = Alo[(r + 8) * ASTR + c];
                al[mi][2] = Alo[r * ASTR + c + 4];
                al[mi][3] = Alo[(r + 8) * ASTR + c + 4];
            }
#pragma unroll
            for (int ni = 0; ni < 4; ni++) {
                int n = wn + ni * 8 + (lane >> 2);
                int k = kk + (lane & 3);
                bhf[ni][0] = Bhi[k * BSTR + n];
                bhf[ni][1] = Bhi[(k + 4) * BSTR + n];
                blf[ni][0] = Blo[k * BSTR + n];
                blf[ni][1] = Blo[(k + 4) * BSTR + n];
            }
#pragma unroll
            for (int mi = 0; mi < 4; mi++)
#pragma unroll
                for (int ni = 0; ni < 4; ni++) {
                    mma_tf32(acc[mi][ni], ah[mi], bhf[ni]);
                    mma_tf32(acc[mi][ni], ah[mi], blf[ni]);
                    mma_tf32(acc[mi][ni], al[mi], bhf[ni]);
                }
        }
        __syncthreads();
    }

    float* O = g_hprime + (size_t)bh * NN * F_OUT;
    unsigned* Ot = g_hprime_t + (size_t)bh * NN * F_OUT;
#pragma unroll
    for (int mi = 0; mi < 4; mi++)
#pragma unroll
        for (int ni = 0; ni < 4; ni++) {
            int r = row0 + wm + mi * 16 + (lane >> 2);
            int c = col0 + wn + ni * 8 + 2 * (lane & 3);
            size_t p0 = (size_t)r * F_OUT + c;
            size_t p1 = (size_t)(r + 8) * F_OUT + c;
            *(float2*)&O[p0] = make_float2(acc[mi][ni][0], acc[mi][ni][1]);
            *(float2*)&O[p1] = make_float2(acc[mi][ni][2], acc[mi][ni][3]);
            *(uint2*)&Ot[p0] = make_uint2(f2tf(acc[mi][ni][0]), f2tf(acc[mi][ni][1]));
            *(uint2*)&Ot[p1] = make_uint2(f2tf(acc[mi][ni][2]), f2tf(acc[mi][ni][3]));
        }
}

// ------------ kernel 2: row dots + factorized exp tables --------------------
__global__ __launch_bounds__(256) void row_dots(const float* __restrict__ a_src,
                                                const float* __restrict__ a_dst) {
    int row = blockIdx.x;
    int hd = (row / NN) % H;
    const float* hp = g_hprime + (size_t)row * F_OUT;
    const float* as = a_src + hd * F_OUT;
    const float* ad = a_dst + hd * F_OUT;
    int tid = threadIdx.x;
    float ps = 0.f, pd = 0.f;
    for (int f = tid; f < F_OUT; f += 256) {
        float t = tanhf(hp[f]);
        ps += t * as[f];
        pd += t * ad[f];
    }
    __shared__ float r1[8], r2[8];
    for (int o = 16; o; o >>= 1) {
        ps += __shfl_down_sync(0xffffffffu, ps, o);
        pd += __shfl_down_sync(0xffffffffu, pd, o);
    }
    if ((tid & 31) == 0) { r1[tid >> 5] = ps; r2[tid >> 5] = pd; }
    __syncthreads();
    if (tid == 0) {
        float s = 0.f, d = 0.f;
        for (int t = 0; t < 8; t++) { s += r1[t]; d += r2[t]; }
        g_E[row] = __expf(s);
        g_G[row] = __expf(0.2f * s);
        g_T[row] = __expf(-s);
        g_F[row] = __expf(d);
        g_Hv[row] = __expf(0.2f * d);
    }
}

// -------- kernel 3: row sums of unnormalized attention, scale E/G -----------
__global__ __launch_bounds__(256) void row_stats() {
    int row = blockIdx.x;
    int i = row % NN;
    int bh = row / NN;
    int b = bh / H;
    const unsigned* mrow = g_mask + ((size_t)b * NN + i) * WPR;
    const float* Fv = g_F + (size_t)bh * NN;
    const float* Hv = g_Hv + (size_t)bh * NN;
    float Ei = g_E[row], Gi = g_G[row], Ti = g_T[row];
    int tid = threadIdx.x;
    float sum = 0.f;
    for (int j = tid; j < NN; j += 256) {
        if ((mrow[j >> 5] >> (j & 31)) & 1u) {
            float Fj = Fv[j];
            sum += (Fj >= Ti) ? Ei * Fj : Gi * Hv[j];
        }
    }
    __shared__ float red[8];
    for (int o = 16; o; o >>= 1) sum += __shfl_down_sync(0xffffffffu, sum, o);
    if ((tid & 31) == 0) red[tid >> 5] = sum;
    __syncthreads();
    if (tid == 0) {
        float t0 = 0.f;
        for (int t = 0; t < 8; t++) t0 += red[t];
        float inv = 1.f / t0;
        g_Es[row] = Ei * inv;
        g_Gs[row] = Gi * inv;
    }
}

// ------------- kernel 4: out = P @ h_prime + bias  (tf32) -------------------
// 128x128 CTA, 256 thr = 8 warps (2m x 4n), warp tile 64x32, BK=16.
__global__ __launch_bounds__(256) void attn_gemm_tc(float* __restrict__ out,
                                                    const float* __restrict__ bias) {
    __shared__ unsigned Asm[128 * ASTR];
    __shared__ unsigned Bsm[16 * BSTR];
    __shared__ float sE[128], sG[128], sT[128];

    int bh = blockIdx.z, b = bh / H;
    int row0 = blockIdx.y * 128, col0 = blockIdx.x * 128;
    const unsigned* Bm = g_hprime_t + (size_t)bh * NN * F_OUT + col0;
    const float* Fv = g_F + (size_t)bh * NN;
    const float* Hv = g_Hv + (size_t)bh * NN;
    const unsigned* mbase = g_mask + ((size_t)b * NN + row0) * WPR;

    int tid = threadIdx.x, lane = tid & 31, warp = tid >> 5;
    if (tid < 128) {
        int r = bh * NN + row0 + tid;
        sE[tid] = g_Es[r];
        sG[tid] = g_Gs[r];
        sT[tid] = g_T[r];
    }
    __syncthreads();

    int wm = (warp & 1) * 64, wn = (warp >> 1) * 32;

    float acc[4][4][4];
#pragma unroll
    for (int mi = 0; mi < 4; mi++)
#pragma unroll
        for (int ni = 0; ni < 4; ni++)
#pragma unroll
            for (int r = 0; r < 4; r++) acc[mi][ni][r] = 0.f;

    int jl = tid & 15, il = tid >> 4;          // P gen: i = il + 16*r (bank-safe)
    int kr = tid >> 4, nc = (tid & 15) * 8;    // B tile load

    for (int k0 = 0; k0 < NN; k0 += 16) {
        float Fj = Fv[k0 + jl], Hj = Hv[k0 + jl];
        int widx = k0 >> 5;
        int bitsh = (k0 & 16) + jl;
#pragma unroll
        for (int r = 0; r < 8; r++) {
            int i = il + 16 * r;
            unsigned mw = mbase[(size_t)i * WPR + widx];
            float p = (Fj >= sT[i]) ? sE[i] * Fj : sG[i] * Hj;
            p = ((mw >> bitsh) & 1u) ? p : 0.f;
            Asm[i * ASTR + jl] = f2tf(p);
        }
        *(uint4*)&Bsm[kr * BSTR + nc]     = *(const uint4*)&Bm[(size_t)(k0 + kr) * F_OUT + nc];
        *(uint4*)&Bsm[kr * BSTR + nc + 4] = *(const uint4*)&Bm[(size_t)(k0 + kr) * F_OUT + nc + 4];
        __syncthreads();
#pragma unroll
        for (int kk = 0; kk < 16; kk += 8) {
            unsigned af[4][4], bf[4][2];
#pragma unroll
            for (int mi = 0; mi < 4; mi++) {
                int r = wm + mi * 16 + (lane >> 2);
                int c = kk + (lane & 3);
                af[mi][0] = Asm[r * ASTR + c];
                af[mi][1] = Asm[(r + 8) * ASTR + c];
                af[mi][2] = Asm[r * ASTR + c + 4];
                af[mi][3] = Asm[(r + 8) * ASTR + c + 4];
            }
#pragma unroll
            for (int ni = 0; ni < 4; ni++) {
                int n = wn + ni * 8 + (lane >> 2);
                int k = kk + (lane & 3);
                bf[ni][0] = Bsm[k * BSTR + n];
                bf[ni][1] = Bsm[(k + 4) * BSTR + n];
            }
#pragma unroll
            for (int mi = 0; mi < 4; mi++)
#pragma unroll
                for (int ni = 0; ni < 4; ni++)
                    mma_tf32(acc[mi][ni], af[mi], bf[ni]);
        }
        __syncthreads();
    }

#pragma unroll
    for (int mi = 0; mi < 4; mi++)
#pragma unroll
        for (int ni = 0; ni < 4; ni++) {
            int r = row0 + wm + mi * 16 + (lane >> 2);
            int c = col0 + wn + ni * 8 + 2 * (lane & 3);
            float b0 = bias[c], b1 = bias[c + 1];
            size_t p0 = ((size_t)bh * NN + r) * F_OUT + c;
            size_t p1 = ((size_t)bh * NN + r + 8) * F_OUT + c;
            *(float2*)&out[p0] = make_float2(acc[mi][ni][0] + b0, acc[mi][ni][1] + b1);
            *(float2*)&out[p1] = make_float2(acc[mi][ni][2] + b0, acc[mi][ni][3] + b1);
        }
}

// ---------------------------------------------------------------------------
extern "C" void kernel_launch(void* const* d_in, const int* in_sizes, int n_in,
                              void* d_out, int out_size) {
    const float* hmat = 0; const void* adj = 0; const float* wmat = 0;
    const float* a_src = 0; const float* a_dst = 0; const float* bias = 0;
    for (int i = 0; i < n_in; i++) {
        long sz = in_sizes[i];
        if (sz == (long)BS * NN * F_IN)        hmat = (const float*)d_in[i];
        else if (sz == (long)BS * NN * NN)     adj  = d_in[i];
        else if (sz == (long)H * F_IN * F_OUT) wmat = (const float*)d_in[i];
        else if (sz == (long)H * F_OUT) {
            if (!a_src) a_src = (const float*)d_in[i];
            else        a_dst = (const float*)d_in[i];
        }
        else if (sz == (long)F_OUT)            bias = (const float*)d_in[i];
    }
    float* out = (float*)d_out;

    detect_adj<<<1, 32>>>((const unsigned int*)adj);
    pack_adj<<<(BS * NN * WPR + 255) / 256, 256>>>(adj);

    // pre-split h and w into tf32 hi/lo
    {
        unsigned *hh, *hl, *wh, *wl;
        cudaGetSymbolAddress((void**)&hh, g_h_hi);
        cudaGetSymbolAddress((void**)&hl, g_h_lo);
        cudaGetSymbolAddress((void**)&wh, g_w_hi);
        cudaGetSymbolAddress((void**)&wl, g_w_lo);
        int nh4 = BS * NN * F_IN / 4, nw4 = H * F_IN * F_OUT / 4;
        split_f32<<<(nh4 + 255) / 256, 256>>>((const float4*)hmat, (uint4*)hh, (uint4*)hl, nh4);
        split_f32<<<(nw4 + 255) / 256, 256>>>((const float4*)wmat, (uint4*)wh, (uint4*)wl, nw4);
    }

    dim3 gGemm(F_OUT / 128, NN / 128, BS * H);  // (6, 16, 8)
    hp_gemm_tc<<<gGemm, 256>>>();
    row_dots<<<BS * H * NN, 256>>>(a_src, a_dst);
    row_stats<<<BS * H * NN, 256>>>();
    attn_gemm_tc<<<gGemm, 256>>>(out, bias);
}

// round 7
// speedup vs baseline: 1.7432x; 1.0457x over previous
#include <cuda_runtime.h>
#include <stdint.h>
#include <math.h>

#define BS 4
#define NN 2048
#define H 2
#define F_IN 768
#define F_OUT 768
#define WPR 64

// ----------------------------- device scratch ------------------------------
__device__ float    g_hprime[BS * H * NN * F_OUT];    // fp32 (row_dots)
__device__ unsigned g_hprime_t[BS * H * NN * F_OUT];  // tf32 (attn B operand)
__device__ unsigned g_h_hi[BS * NN * F_IN], g_h_lo[BS * NN * F_IN];
__device__ unsigned g_w_hi[H * F_IN * F_OUT], g_w_lo[H * F_IN * F_OUT];
__device__ float g_E[BS * H * NN], g_G[BS * H * NN], g_T[BS * H * NN];
__device__ float g_F[BS * H * NN], g_Hv[BS * H * NN];
__device__ float g_Es[BS * H * NN], g_Gs[BS * H * NN];
__device__ unsigned g_mask[BS * NN * WPR];     // [b][i][w]
__device__ unsigned g_maskT[BS * WPR * NN];    // [b][w][i]
__device__ int g_is_i32;

// ------------------------------- helpers ------------------------------------
__device__ __forceinline__ unsigned f2tf(float x) {
    unsigned r;
    asm("cvt.rna.tf32.f32 %0, %1;" : "=r"(r) : "f"(x));
    return r;
}
__device__ __forceinline__ void mma_tf32(float* d, const unsigned* a, const unsigned* b) {
    asm volatile(
        "mma.sync.aligned.m16n8k8.row.col.f32.tf32.tf32.f32 "
        "{%0,%1,%2,%3}, {%4,%5,%6,%7}, {%8,%9}, {%0,%1,%2,%3};"
        : "+f"(d[0]), "+f"(d[1]), "+f"(d[2]), "+f"(d[3])
        : "r"(a[0]), "r"(a[1]), "r"(a[2]), "r"(a[3]), "r"(b[0]), "r"(b[1]));
}

// ---- fragment-permuted smem layout (A: 128x16 tile, B: 16x128 tile) --------
// A element (r,c): lane=(r&7)*4+(c&3), reg=((r>>3)&1)+2*((c>>2)&1)
//   unit = ((r>>4)*2 + (c>>3))*32 + lane, swizzled ^ (lane>>3); addr=unit*4+reg
// B element (k,n): lane=(n&7)*4+(k&3), reg=(k>>2)&1
//   unit = ((n>>3)*2 + (k>>3))*32 + lane, swizzled ^ ((n>>3 & 7)*2); addr=unit*2+reg

__device__ __forceinline__ void scatterA(unsigned* s, int r, int c0, uint4 v) {
    int t = (r & 7) >> 1;
    int X = ((((r >> 4) * 2 + (c0 >> 3)) * 32 + (r & 7) * 4) << 2)
            + ((r >> 3) & 1) + (((c0 >> 2) & 1) << 1);
    s[X + ((0 ^ t) << 2)] = v.x;
    s[X + ((1 ^ t) << 2)] = v.y;
    s[X + ((2 ^ t) << 2)] = v.z;
    s[X + ((3 ^ t) << 2)] = v.w;
}
__device__ __forceinline__ void scatterB(unsigned* s, int k, int n0, uint4 v) {
    int nblk = n0 >> 3;
    int cx = (nblk & 7) * 2;
    int base = (nblk * 2 + ((k >> 3) & 1)) * 32 + (n0 & 7) * 4 + (k & 3);
    int reg = (k >> 2) & 1;
    s[(((base     ) ^ cx) << 1) + reg] = v.x;
    s[(((base +  4) ^ cx) << 1) + reg] = v.y;
    s[(((base +  8) ^ cx) << 1) + reg] = v.z;
    s[(((base + 12) ^ cx) << 1) + reg] = v.w;
}
__device__ __forceinline__ uint4 fragA(const unsigned* s, int mblk, int kk, int lane) {
    int u = ((mblk * 2 + kk) * 32 + lane) ^ (lane >> 3);
    return *(const uint4*)&s[u << 2];
}
__device__ __forceinline__ uint2 fragB(const unsigned* s, int nblk, int kk, int lane) {
    int u = ((nblk * 2 + kk) * 32 + lane) ^ ((nblk & 7) * 2);
    return *(const uint2*)&s[u << 1];
}

// ----------------------- kernel 0a: adjacency dtype -------------------------
__global__ void detect_adj(const unsigned* __restrict__ adj) {
    if (threadIdx.x == 0 && blockIdx.x == 0) {
        int ok = 1;
        for (int i = 0; i < 64; i++)
            if (adj[i] > 1u) ok = 0;
        g_is_i32 = ok;
    }
}

// ----------------------- kernel 0b: pack adjacency --------------------------
__global__ __launch_bounds__(256) void pack_adj(const void* __restrict__ adjraw) {
    int idx = blockIdx.x * blockDim.x + threadIdx.x;
    if (idx >= BS * NN * WPR) return;
    int w = idx % WPR;
    int i = (idx / WPR) % NN;
    int b = idx / (WPR * NN);
    size_t base = (size_t)(idx / WPR) * NN + (size_t)w * 32;
    unsigned bits = 0;
    if (g_is_i32) {
        const uint4* p = (const uint4*)((const unsigned*)adjraw + base);
#pragma unroll
        for (int q = 0; q < 8; q++) {
            uint4 v = p[q];
            bits |= (unsigned)(v.x != 0) << (4 * q);
            bits |= (unsigned)(v.y != 0) << (4 * q + 1);
            bits |= (unsigned)(v.z != 0) << (4 * q + 2);
            bits |= (unsigned)(v.w != 0) << (4 * q + 3);
        }
    } else {
        const unsigned char* p = (const unsigned char*)adjraw + base;
#pragma unroll
        for (int t = 0; t < 32; t++) bits |= (unsigned)(p[t] != 0) << t;
    }
    if ((i >> 5) == w) bits |= 1u << (i & 31);
    g_mask[idx] = bits;
    g_maskT[((size_t)b * WPR + w) * NN + i] = bits;
}

// ------------------- kernel 0c: fp32 -> (tf32 hi, tf32 lo) ------------------
__global__ __launch_bounds__(256) void split_f32(const float4* __restrict__ src,
                                                 uint4* __restrict__ hi,
                                                 uint4* __restrict__ lo, int n4) {
    int i = blockIdx.x * blockDim.x + threadIdx.x;
    if (i >= n4) return;
    float4 v = src[i];
    uint4 h, l;
    h.x = f2tf(v.x); l.x = f2tf(v.x - __uint_as_float(h.x));
    h.y = f2tf(v.y); l.y = f2tf(v.y - __uint_as_float(h.y));
    h.z = f2tf(v.z); l.z = f2tf(v.z - __uint_as_float(h.z));
    h.w = f2tf(v.w); l.w = f2tf(v.w - __uint_as_float(h.w));
    hi[i] = h;
    lo[i] = l;
}

// ------------------- kernel 1: h_prime = h @ w  (3xTF32) --------------------
// 128x128 CTA, 256 thr = 8 warps (2m x 4n), BK=16, double-buffered.
#define C_HP (F_IN / 16)
#define STG_HP 8192   // u32 per stage: Ahi 2048 | Alo 2048 | Bhi 2048 | Blo 2048

__global__ __launch_bounds__(256) void hp_gemm_tc() {
    extern __shared__ unsigned sm[];
    int bh = blockIdx.z, b = bh / H, hd = bh % H;
    int row0 = blockIdx.y * 128, col0 = blockIdx.x * 128;
    const unsigned* Ah = g_h_hi + ((size_t)b * NN + row0) * F_IN;
    const unsigned* Al = g_h_lo + ((size_t)b * NN + row0) * F_IN;
    const unsigned* Bh = g_w_hi + (size_t)hd * F_IN * F_OUT + col0;
    const unsigned* Bl = g_w_lo + (size_t)hd * F_IN * F_OUT + col0;

    int tid = threadIdx.x, lane = tid & 31, warp = tid >> 5;
    int wm = (warp & 1) * 64, wn = (warp >> 1) * 32;
    int mb0 = wm >> 4, nb0 = wn >> 3;
    int ar = tid >> 1, ac = (tid & 1) * 8;
    int kr = tid >> 4, nc = (tid & 15) * 8;

    float acc[4][4][4];
#pragma unroll
    for (int mi = 0; mi < 4; mi++)
#pragma unroll
        for (int ni = 0; ni < 4; ni++)
#pragma unroll
            for (int r = 0; r < 4; r++) acc[mi][ni][r] = 0.f;

    uint4 pAh0, pAh1, pAl0, pAl1, pBh0, pBh1, pBl0, pBl1;
#define LOADG(k0)                                                          \
    do {                                                                   \
        size_t ga = (size_t)ar * F_IN + (k0) + ac;                         \
        pAh0 = *(const uint4*)&Ah[ga]; pAh1 = *(const uint4*)&Ah[ga + 4];  \
        pAl0 = *(const uint4*)&Al[ga]; pAl1 = *(const uint4*)&Al[ga + 4];  \
        size_t gb = (size_t)((k0) + kr) * F_OUT + nc;                      \
        pBh0 = *(const uint4*)&Bh[gb]; pBh1 = *(const uint4*)&Bh[gb + 4];  \
        pBl0 = *(const uint4*)&Bl[gb]; pBl1 = *(const uint4*)&Bl[gb + 4];  \
    } while (0)
#define SCAT(st)                                                           \
    do {                                                                   \
        scatterA((st),        ar, ac,     pAh0); scatterA((st),        ar, ac + 4, pAh1); \
        scatterA((st) + 2048, ar, ac,     pAl0); scatterA((st) + 2048, ar, ac + 4, pAl1); \
        scatterB((st) + 4096, kr, nc,     pBh0); scatterB((st) + 4096, kr, nc + 4, pBh1); \
        scatterB((st) + 6144, kr, nc,     pBl0); scatterB((st) + 6144, kr, nc + 4, pBl1); \
    } while (0)

    LOADG(0);
    SCAT(sm);
    __syncthreads();

    for (int c = 0; c < C_HP; c++) {
        unsigned* st = sm + (c & 1) * STG_HP;
        if (c + 1 < C_HP) LOADG((c + 1) * 16);
#pragma unroll
        for (int kk = 0; kk < 2; kk++) {
            unsigned a_h[4][4], a_l[4][4], b_h[4][2], b_l[4][2];
#pragma unroll
            for (int mi = 0; mi < 4; mi++) {
                uint4 vh = fragA(st, mb0 + mi, kk, lane);
                a_h[mi][0] = vh.x; a_h[mi][1] = vh.y; a_h[mi][2] = vh.z; a_h[mi][3] = vh.w;
                uint4 vl = fragA(st + 2048, mb0 + mi, kk, lane);
                a_l[mi][0] = vl.x; a_l[mi][1] = vl.y; a_l[mi][2] = vl.z; a_l[mi][3] = vl.w;
            }
#pragma unroll
            for (int ni = 0; ni < 4; ni++) {
                uint2 vh = fragB(st + 4096, nb0 + ni, kk, lane);
                b_h[ni][0] = vh.x; b_h[ni][1] = vh.y;
                uint2 vl = fragB(st + 6144, nb0 + ni, kk, lane);
                b_l[ni][0] = vl.x; b_l[ni][1] = vl.y;
            }
#pragma unroll
            for (int mi = 0; mi < 4; mi++)
#pragma unroll
                for (int ni = 0; ni < 4; ni++) {
                    mma_tf32(acc[mi][ni], a_h[mi], b_h[ni]);
                    mma_tf32(acc[mi][ni], a_h[mi], b_l[ni]);
                    mma_tf32(acc[mi][ni], a_l[mi], b_h[ni]);
                }
        }
        if (c + 1 < C_HP) SCAT(sm + ((c + 1) & 1) * STG_HP);
        __syncthreads();
    }
#undef LOADG
#undef SCAT

    float* O = g_hprime + (size_t)bh * NN * F_OUT;
    unsigned* Ot = g_hprime_t + (size_t)bh * NN * F_OUT;
#pragma unroll
    for (int mi = 0; mi < 4; mi++)
#pragma unroll
        for (int ni = 0; ni < 4; ni++) {
            int r = row0 + wm + mi * 16 + (lane >> 2);
            int cc = col0 + wn + ni * 8 + 2 * (lane & 3);
            size_t p0 = (size_t)r * F_OUT + cc;
            size_t p1 = (size_t)(r + 8) * F_OUT + cc;
            *(float2*)&O[p0] = make_float2(acc[mi][ni][0], acc[mi][ni][1]);
            *(float2*)&O[p1] = make_float2(acc[mi][ni][2], acc[mi][ni][3]);
            *(uint2*)&Ot[p0] = make_uint2(f2tf(acc[mi][ni][0]), f2tf(acc[mi][ni][1]));
            *(uint2*)&Ot[p1] = make_uint2(f2tf(acc[mi][ni][2]), f2tf(acc[mi][ni][3]));
        }
}

// ------------ kernel 2: row dots + factorized exp tables --------------------
__global__ __launch_bounds__(256) void row_dots(const float* __restrict__ a_src,
                                                const float* __restrict__ a_dst) {
    int row = blockIdx.x;
    int hd = (row / NN) % H;
    const float* hp = g_hprime + (size_t)row * F_OUT;
    const float* as = a_src + hd * F_OUT;
    const float* ad = a_dst + hd * F_OUT;
    int tid = threadIdx.x;
    float ps = 0.f, pd = 0.f;
    for (int f = tid; f < F_OUT; f += 256) {
        float t = tanhf(hp[f]);
        ps += t * as[f];
        pd += t * ad[f];
    }
    __shared__ float r1[8], r2[8];
    for (int o = 16; o; o >>= 1) {
        ps += __shfl_down_sync(0xffffffffu, ps, o);
        pd += __shfl_down_sync(0xffffffffu, pd, o);
    }
    if ((tid & 31) == 0) { r1[tid >> 5] = ps; r2[tid >> 5] = pd; }
    __syncthreads();
    if (tid == 0) {
        float s = 0.f, d = 0.f;
        for (int t = 0; t < 8; t++) { s += r1[t]; d += r2[t]; }
        g_E[row] = __expf(s);
        g_G[row] = __expf(0.2f * s);
        g_T[row] = __expf(-s);
        g_F[row] = __expf(d);
        g_Hv[row] = __expf(0.2f * d);
    }
}

// -------- kernel 3: row sums of unnormalized attention, scale E/G -----------
__global__ __launch_bounds__(256) void row_stats() {
    int row = blockIdx.x;
    int i = row % NN;
    int bh = row / NN;
    int b = bh / H;
    const unsigned* mrow = g_mask + ((size_t)b * NN + i) * WPR;
    const float* Fv = g_F + (size_t)bh * NN;
    const float* Hv = g_Hv + (size_t)bh * NN;
    float Ei = g_E[row], Gi = g_G[row], Ti = g_T[row];
    int tid = threadIdx.x;
    float sum = 0.f;
    for (int j = tid; j < NN; j += 256) {
        if ((mrow[j >> 5] >> (j & 31)) & 1u) {
            float Fj = Fv[j];
            sum += (Fj >= Ti) ? Ei * Fj : Gi * Hv[j];
        }
    }
    __shared__ float red[8];
    for (int o = 16; o; o >>= 1) sum += __shfl_down_sync(0xffffffffu, sum, o);
    if ((tid & 31) == 0) red[tid >> 5] = sum;
    __syncthreads();
    if (tid == 0) {
        float t0 = 0.f;
        for (int t = 0; t < 8; t++) t0 += red[t];
        float inv = 1.f / t0;
        g_Es[row] = Ei * inv;
        g_Gs[row] = Gi * inv;
    }
}

// ------------- kernel 4: out = P @ h_prime + bias  (tf32) -------------------
#define C_AT (NN / 16)
#define STG_AT 4096   // u32 per stage: A 2048 | B 2048

__global__ __launch_bounds__(256) void attn_gemm_tc(float* __restrict__ out,
                                                    const float* __restrict__ bias) {
    extern __shared__ unsigned sm[];
    __shared__ float sT[128], sEs[128], sGs[128];

    int bh = blockIdx.z, b = bh / H;
    int row0 = blockIdx.y * 128, col0 = blockIdx.x * 128;
    const unsigned* Bm = g_hprime_t + (size_t)bh * NN * F_OUT + col0;
    const float* Fv = g_F + (size_t)bh * NN;
    const float* Hv = g_Hv + (size_t)bh * NN;

    int tid = threadIdx.x, lane = tid & 31, warp = tid >> 5;
    if (tid < 128) {
        int r = bh * NN + row0 + tid;
        sT[tid] = g_T[r];
        sEs[tid] = g_Es[r];
        sGs[tid] = g_Gs[r];
    }
    __syncthreads();

    int wm = (warp & 1) * 64, wn = (warp >> 1) * 32;
    int mb0 = wm >> 4, nb0 = wn >> 3;
    int jl = tid & 15, iblk = tid >> 4;       // P-gen coords
    int kr = tid >> 4, nc = (tid & 15) * 8;   // B loader coords

    float acc[4][4][4];
#pragma unroll
    for (int mi = 0; mi < 4; mi++)
#pragma unroll
        for (int ni = 0; ni < 4; ni++)
#pragma unroll
            for (int r = 0; r < 4; r++) acc[mi][ni][r] = 0.f;

    uint4 pB0, pB1;
#define LOADB(k0)                                                      \
    do {                                                               \
        size_t gb = (size_t)((k0) + kr) * F_OUT + nc;                  \
        pB0 = *(const uint4*)&Bm[gb]; pB1 = *(const uint4*)&Bm[gb + 4];\
    } while (0)
#define GENP(st, k0)                                                                \
    do {                                                                            \
        int j = (k0) + jl;                                                          \
        float Fj = Fv[j], Hj = Hv[j];                                               \
        const unsigned* mT = g_maskT + ((size_t)b * WPR + (j >> 5)) * NN            \
                             + row0 + iblk * 8;                                     \
        int bitp = j & 31;                                                          \
        _Pragma("unroll")                                                           \
        for (int rr = 0; rr < 8; rr++) {                                            \
            int i = iblk * 8 + rr;                                                  \
            float p = 0.f;                                                          \
            if ((mT[rr] >> bitp) & 1u)                                              \
                p = (Fj >= sT[i]) ? sEs[i] * Fj : sGs[i] * Hj;                      \
            int tt = (i & 7) >> 1;                                                  \
            int X = ((((i >> 4) * 2 + (jl >> 3)) * 32 + (i & 7) * 4) << 2)          \
                    + ((i >> 3) & 1) + (((jl >> 2) & 1) << 1);                      \
            (st)[X + (((jl & 3) ^ tt) << 2)] = f2tf(p);                             \
        }                                                                           \
    } while (0)

    LOADB(0);
    GENP(sm, 0);
    scatterB(sm + 2048, kr, nc, pB0);
    scatterB(sm + 2048, kr, nc + 4, pB1);
    __syncthreads();

    for (int c = 0; c < C_AT; c++) {
        unsigned* st = sm + (c & 1) * STG_AT;
        if (c + 1 < C_AT) LOADB((c + 1) * 16);
#pragma unroll
        for (int kk = 0; kk < 2; kk++) {
            unsigned a_f[4][4], b_f[4][2];
#pragma unroll
            for (int mi = 0; mi < 4; mi++) {
                uint4 v = fragA(st, mb0 + mi, kk, lane);
                a_f[mi][0] = v.x; a_f[mi][1] = v.y; a_f[mi][2] = v.z; a_f[mi][3] = v.w;
            }
#pragma unroll
            for (int ni = 0; ni < 4; ni++) {
                uint2 v = fragB(st + 2048, nb0 + ni, kk, lane);
                b_f[ni][0] = v.x; b_f[ni][1] = v.y;
            }
#pragma unroll
            for (int mi = 0; mi < 4; mi++)
#pragma unroll
                for (int ni = 0; ni < 4; ni++)
                    mma_tf32(acc[mi][ni], a_f[mi], b_f[ni]);
        }
        if (c + 1 < C_AT) {
            unsigned* st2 = sm + ((c + 1) & 1) * STG_AT;
            GENP(st2, (c + 1) * 16);
            scatterB(st2 + 2048, kr, nc, pB0);
            scatterB(st2 + 2048, kr, nc + 4, pB1);
        }
        __syncthreads();
    }
#undef LOADB
#undef GENP

#pragma unroll
    for (int mi = 0; mi < 4; mi++)
#pragma unroll
        for (int ni = 0; ni < 4; ni++) {
            int r = row0 + wm + mi * 16 + (lane >> 2);
            int cc = col0 + wn + ni * 8 + 2 * (lane & 3);
            float b0 = bias[cc], b1 = bias[cc + 1];
            size_t p0 = ((size_t)bh * NN + r) * F_OUT + cc;
            size_t p1 = ((size_t)bh * NN + r + 8) * F_OUT + cc;
            *(float2*)&out[p0] = make_float2(acc[mi][ni][0] + b0, acc[mi][ni][1] + b1);
            *(float2*)&out[p1] = make_float2(acc[mi][ni][2] + b0, acc[mi][ni][3] + b1);
        }
}

// ---------------------------------------------------------------------------
extern "C" void kernel_launch(void* const* d_in, const int* in_sizes, int n_in,
                              void* d_out, int out_size) {
    const float* hmat = 0; const void* adj = 0; const float* wmat = 0;
    const float* a_src = 0; const float* a_dst = 0; const float* bias = 0;
    for (int i = 0; i < n_in; i++) {
        long sz = in_sizes[i];
        if (sz == (long)BS * NN * F_IN)        hmat = (const float*)d_in[i];
        else if (sz == (long)BS * NN * NN)     adj  = d_in[i];
        else if (sz == (long)H * F_IN * F_OUT) wmat = (const float*)d_in[i];
        else if (sz == (long)H * F_OUT) {
            if (!a_src) a_src = (const float*)d_in[i];
            else        a_dst = (const float*)d_in[i];
        }
        else if (sz == (long)F_OUT)            bias = (const float*)d_in[i];
    }
    float* out = (float*)d_out;

    static int attr_done = 0;
    if (!attr_done) {
        cudaFuncSetAttribute(hp_gemm_tc, cudaFuncAttributeMaxDynamicSharedMemorySize,
                             2 * STG_HP * 4);
        cudaFuncSetAttribute(attn_gemm_tc, cudaFuncAttributeMaxDynamicSharedMemorySize,
                             2 * STG_AT * 4);
        attr_done = 1;
    }

    detect_adj<<<1, 32>>>((const unsigned*)adj);
    pack_adj<<<(BS * NN * WPR + 255) / 256, 256>>>(adj);

    unsigned *hh, *hl, *wh, *wl;
    cudaGetSymbolAddress((void**)&hh, g_h_hi);
    cudaGetSymbolAddress((void**)&hl, g_h_lo);
    cudaGetSymbolAddress((void**)&wh, g_w_hi);
    cudaGetSymbolAddress((void**)&wl, g_w_lo);
    int nh4 = BS * NN * F_IN / 4, nw4 = H * F_IN * F_OUT / 4;
    split_f32<<<(nh4 + 255) / 256, 256>>>((const float4*)hmat, (uint4*)hh, (uint4*)hl, nh4);
    split_f32<<<(nw4 + 255) / 256, 256>>>((const float4*)wmat, (uint4*)wh, (uint4*)wl, nw4);

    dim3 gGemm(F_OUT / 128, NN / 128, BS * H);  // (6, 16, 8)
    hp_gemm_tc<<<gGemm, 256, 2 * STG_HP * 4>>>();
    row_dots<<<BS * H * NN, 256>>>(a_src, a_dst);
    row_stats<<<BS * H * NN, 256>>>();
    attn_gemm_tc<<<gGemm, 256, 2 * STG_AT * 4>>>(out, bias);
}

// round 8
// speedup vs baseline: 2.4275x; 1.3926x over previous
#include <cuda_runtime.h>
#include <cuda_fp16.h>
#include <stdint.h>
#include <math.h>

#define BS 4
#define NN 2048
#define H 2
#define F_IN 768
#define F_OUT 768
#define WPR 64

// ----------------------------- device scratch ------------------------------
__device__ float    g_hprime[BS * H * NN * F_OUT];          // fp32 (row_dots)
__device__ unsigned g_h16_hi[BS * NN * F_IN / 2];           // f16x2 pairs along k
__device__ unsigned g_h16_lo[BS * NN * F_IN / 2];
__device__ unsigned g_wT_hi[H * F_OUT * F_IN / 2];          // [hd][n][kpair]
__device__ unsigned g_wT_lo[H * F_OUT * F_IN / 2];
__device__ unsigned g_hpT[BS * H * F_OUT * NN / 2];         // [bh][n][jpair] f16
__device__ float g_E[BS * H * NN], g_G[BS * H * NN], g_T[BS * H * NN];
__device__ float g_F[BS * H * NN], g_Hv[BS * H * NN];
__device__ float g_Es[BS * H * NN], g_Gs[BS * H * NN];
__device__ unsigned g_mask[BS * NN * WPR];     // [b][i][w]
__device__ unsigned g_maskT[BS * WPR * NN];    // [b][w][i]
__device__ int g_is_i32;

// ------------------------------- helpers ------------------------------------
__device__ __forceinline__ unsigned packh(__half a, __half b) {
    __half2 t = __halves2half2(a, b);
    return *(unsigned*)&t;
}
__device__ __forceinline__ unsigned h2pack(float a, float b) {
    __half2 t = __floats2half2_rn(a, b);
    return *(unsigned*)&t;
}
__device__ __forceinline__ void h2split(float x, __half& hi, __half& lo) {
    hi = __float2half_rn(x);
    lo = __float2half_rn(x - __half2float(hi));
}
__device__ __forceinline__ void mma_f16(float* d, const unsigned* a, const unsigned* b) {
    asm volatile(
        "mma.sync.aligned.m16n8k16.row.col.f32.f16.f16.f32 "
        "{%0,%1,%2,%3}, {%4,%5,%6,%7}, {%8,%9}, {%0,%1,%2,%3};"
        : "+f"(d[0]), "+f"(d[1]), "+f"(d[2]), "+f"(d[3])
        : "r"(a[0]), "r"(a[1]), "r"(a[2]), "r"(a[3]), "r"(b[0]), "r"(b[1]));
}

// ---- fragment-permuted smem layout (u32 = f16 k-pair) ----------------------
// A tile 128 rows x 16 kpairs; B tile 16 kpairs x 128 n. Same index structure
// as R7 tf32 layout with "c"/"k" meaning kpair index 0..15.
__device__ __forceinline__ void scatterA(unsigned* s, int r, int c0, uint4 v) {
    int t = (r & 7) >> 1;
    int X = ((((r >> 4) * 2 + (c0 >> 3)) * 32 + (r & 7) * 4) << 2)
            + ((r >> 3) & 1) + (((c0 >> 2) & 1) << 1);
    s[X + ((0 ^ t) << 2)] = v.x;
    s[X + ((1 ^ t) << 2)] = v.y;
    s[X + ((2 ^ t) << 2)] = v.z;
    s[X + ((3 ^ t) << 2)] = v.w;
}
// 4 consecutive kpairs (kp0 multiple of 4) for fixed n
__device__ __forceinline__ void scatterBT(unsigned* s, int kp0, int n, uint4 v) {
    int nblk = n >> 3;
    int cx = (nblk & 7) * 2;
    int reg = (kp0 >> 2) & 1;
    int base = (nblk * 2 + (kp0 >> 3)) * 32 + (n & 7) * 4;
    s[(((base + 0) ^ cx) << 1) + reg] = v.x;
    s[(((base + 1) ^ cx) << 1) + reg] = v.y;
    s[(((base + 2) ^ cx) << 1) + reg] = v.z;
    s[(((base + 3) ^ cx) << 1) + reg] = v.w;
}
__device__ __forceinline__ uint4 fragA(const unsigned* s, int mblk, int kk, int lane) {
    int u = ((mblk * 2 + kk) * 32 + lane) ^ (lane >> 3);
    return *(const uint4*)&s[u << 2];
}
__device__ __forceinline__ uint2 fragB(const unsigned* s, int nblk, int kk, int lane) {
    int u = ((nblk * 2 + kk) * 32 + lane) ^ ((nblk & 7) * 2);
    return *(const uint2*)&s[u << 1];
}

// ----------------------- kernel 0a: adjacency dtype -------------------------
__global__ void detect_adj(const unsigned* __restrict__ adj) {
    if (threadIdx.x == 0 && blockIdx.x == 0) {
        int ok = 1;
        for (int i = 0; i < 64; i++)
            if (adj[i] > 1u) ok = 0;
        g_is_i32 = ok;
    }
}

// ----------------------- kernel 0b: pack adjacency --------------------------
__global__ __launch_bounds__(256) void pack_adj(const void* __restrict__ adjraw) {
    int idx = blockIdx.x * blockDim.x + threadIdx.x;
    if (idx >= BS * NN * WPR) return;
    int w = idx % WPR;
    int i = (idx / WPR) % NN;
    int b = idx / (WPR * NN);
    size_t base = (size_t)(idx / WPR) * NN + (size_t)w * 32;
    unsigned bits = 0;
    if (g_is_i32) {
        const uint4* p = (const uint4*)((const unsigned*)adjraw + base);
#pragma unroll
        for (int q = 0; q < 8; q++) {
            uint4 v = p[q];
            bits |= (unsigned)(v.x != 0) << (4 * q);
            bits |= (unsigned)(v.y != 0) << (4 * q + 1);
            bits |= (unsigned)(v.z != 0) << (4 * q + 2);
            bits |= (unsigned)(v.w != 0) << (4 * q + 3);
        }
    } else {
        const unsigned char* p = (const unsigned char*)adjraw + base;
#pragma unroll
        for (int t = 0; t < 32; t++) bits |= (unsigned)(p[t] != 0) << t;
    }
    if ((i >> 5) == w) bits |= 1u << (i & 31);
    g_mask[idx] = bits;
    g_maskT[((size_t)b * WPR + w) * NN + i] = bits;
}

// ------------------ kernel 0c: h fp32 -> f16 hi/lo k-pairs ------------------
__global__ __launch_bounds__(256) void split_h16(const float4* __restrict__ src, int n4) {
    int i = blockIdx.x * blockDim.x + threadIdx.x;
    if (i >= n4) return;
    float4 v = src[i];
    __half hx, lx, hy, ly, hz, lz, hw, lw;
    h2split(v.x, hx, lx); h2split(v.y, hy, ly);
    h2split(v.z, hz, lz); h2split(v.w, hw, lw);
    ((uint2*)g_h16_hi)[i] = make_uint2(packh(hx, hy), packh(hz, hw));
    ((uint2*)g_h16_lo)[i] = make_uint2(packh(lx, ly), packh(lz, lw));
}

// --- kernel 0d: transpose fp32 [z][R][C] -> f16-pair [z][C][R/2] (hi/opt lo) -
__global__ __launch_bounds__(256) void tsp16(const float* __restrict__ src,
                                             unsigned* __restrict__ dhi,
                                             unsigned* __restrict__ dlo,
                                             int R, int C) {
    __shared__ float t[32][33];
    int r0 = blockIdx.y * 32, c0 = blockIdx.x * 32, z = blockIdx.z;
    const float* S = src + ((size_t)z * R + r0) * C + c0;
    int tid = threadIdx.x;
    int cl = tid & 31, rl = tid >> 5;
#pragma unroll
    for (int k = 0; k < 4; k++) t[rl + 8 * k][cl] = S[(size_t)(rl + 8 * k) * C + cl];
    __syncthreads();
    int jj = (tid & 15) * 2, cc = tid >> 4;
#pragma unroll
    for (int k = 0; k < 2; k++) {
        int c = cc + 16 * k;
        float v0 = t[jj][c], v1 = t[jj + 1][c];
        size_t e = ((size_t)z * C + c0 + c) * (R / 2) + (r0 + jj) / 2;
        if (dlo) {
            __half h0, l0, h1, l1;
            h2split(v0, h0, l0); h2split(v1, h1, l1);
            dhi[e] = packh(h0, h1);
            dlo[e] = packh(l0, l1);
        } else {
            dhi[e] = h2pack(v0, v1);
        }
    }
}

// ------------------ kernel 1: h_prime = h @ w  (3-pass fp16) ----------------
// 128x128 CTA, 256 thr = 8 warps (2m x 4n), BK=32 f16 (16 u32), double-buffered.
#define C_HP (F_IN / 32)
#define STG_HP 8192   // u32 per stage: Ahi 2048 | Alo 2048 | Bhi 2048 | Blo 2048

__global__ __launch_bounds__(256) void hp_gemm_f16() {
    extern __shared__ unsigned sm[];
    int bh = blockIdx.z, b = bh / H, hd = bh % H;
    int row0 = blockIdx.y * 128, col0 = blockIdx.x * 128;
    const unsigned* Ah = g_h16_hi + ((size_t)b * NN + row0) * (F_IN / 2);
    const unsigned* Al = g_h16_lo + ((size_t)b * NN + row0) * (F_IN / 2);
    const unsigned* Bh = g_wT_hi + ((size_t)hd * F_OUT + col0) * (F_IN / 2);
    const unsigned* Bl = g_wT_lo + ((size_t)hd * F_OUT + col0) * (F_IN / 2);

    int tid = threadIdx.x, lane = tid & 31, warp = tid >> 5;
    int wm = (warp & 1) * 64, wn = (warp >> 1) * 32;
    int mb0 = wm >> 4, nb0 = wn >> 3;
    int ar = tid >> 1, ac = (tid & 1) * 8;   // A: row, kpair base
    int bn = tid >> 1, bk = (tid & 1) * 8;   // B: n, kpair base

    float acc[4][4][4];
#pragma unroll
    for (int mi = 0; mi < 4; mi++)
#pragma unroll
        for (int ni = 0; ni < 4; ni++)
#pragma unroll
            for (int r = 0; r < 4; r++) acc[mi][ni][r] = 0.f;

    uint4 pAh0, pAh1, pAl0, pAl1, pBh0, pBh1, pBl0, pBl1;
#define LOADG(c)                                                           \
    do {                                                                   \
        size_t ga = (size_t)ar * (F_IN / 2) + (c) * 16 + ac;               \
        pAh0 = *(const uint4*)&Ah[ga]; pAh1 = *(const uint4*)&Ah[ga + 4];  \
        pAl0 = *(const uint4*)&Al[ga]; pAl1 = *(const uint4*)&Al[ga + 4];  \
        size_t gb = (size_t)bn * (F_IN / 2) + (c) * 16 + bk;               \
        pBh0 = *(const uint4*)&Bh[gb]; pBh1 = *(const uint4*)&Bh[gb + 4];  \
        pBl0 = *(const uint4*)&Bl[gb]; pBl1 = *(const uint4*)&Bl[gb + 4];  \
    } while (0)
#define SCAT(st)                                                                          \
    do {                                                                                  \
        scatterA((st),        ar, ac,     pAh0); scatterA((st),        ar, ac + 4, pAh1); \
        scatterA((st) + 2048, ar, ac,     pAl0); scatterA((st) + 2048, ar, ac + 4, pAl1); \
        scatterBT((st) + 4096, bk, bn, pBh0); scatterBT((st) + 4096, bk + 4, bn, pBh1);   \
        scatterBT((st) + 6144, bk, bn, pBl0); scatterBT((st) + 6144, bk + 4, bn, pBl1);   \
    } while (0)

    LOADG(0);
    SCAT(sm);
    __syncthreads();

    for (int c = 0; c < C_HP; c++) {
        unsigned* st = sm + (c & 1) * STG_HP;
        if (c + 1 < C_HP) LOADG(c + 1);
#pragma unroll
        for (int kk = 0; kk < 2; kk++) {
            unsigned a_h[4][4], a_l[4][4], b_h[4][2], b_l[4][2];
#pragma unroll
            for (int mi = 0; mi < 4; mi++) {
                uint4 vh = fragA(st, mb0 + mi, kk, lane);
                a_h[mi][0] = vh.x; a_h[mi][1] = vh.y; a_h[mi][2] = vh.z; a_h[mi][3] = vh.w;
                uint4 vl = fragA(st + 2048, mb0 + mi, kk, lane);
                a_l[mi][0] = vl.x; a_l[mi][1] = vl.y; a_l[mi][2] = vl.z; a_l[mi][3] = vl.w;
            }
#pragma unroll
            for (int ni = 0; ni < 4; ni++) {
                uint2 vh = fragB(st + 4096, nb0 + ni, kk, lane);
                b_h[ni][0] = vh.x; b_h[ni][1] = vh.y;
                uint2 vl = fragB(st + 6144, nb0 + ni, kk, lane);
                b_l[ni][0] = vl.x; b_l[ni][1] = vl.y;
            }
#pragma unroll
            for (int mi = 0; mi < 4; mi++)
#pragma unroll
                for (int ni = 0; ni < 4; ni++) {
                    mma_f16(acc[mi][ni], a_h[mi], b_h[ni]);
                    mma_f16(acc[mi][ni], a_h[mi], b_l[ni]);
                    mma_f16(acc[mi][ni], a_l[mi], b_h[ni]);
                }
        }
        if (c + 1 < C_HP) SCAT(sm + ((c + 1) & 1) * STG_HP);
        __syncthreads();
    }
#undef LOADG
#undef SCAT

    float* O = g_hprime + (size_t)bh * NN * F_OUT;
#pragma unroll
    for (int mi = 0; mi < 4; mi++)
#pragma unroll
        for (int ni = 0; ni < 4; ni++) {
            int r = row0 + wm + mi * 16 + (lane >> 2);
            int cc = col0 + wn + ni * 8 + 2 * (lane & 3);
            *(float2*)&O[(size_t)r * F_OUT + cc] =
                make_float2(acc[mi][ni][0], acc[mi][ni][1]);
            *(float2*)&O[(size_t)(r + 8) * F_OUT + cc] =
                make_float2(acc[mi][ni][2], acc[mi][ni][3]);
        }
}

// ------------ kernel 2: row dots + factorized exp tables --------------------
__global__ __launch_bounds__(256) void row_dots(const float* __restrict__ a_src,
                                                const float* __restrict__ a_dst) {
    int row = blockIdx.x;
    int hd = (row / NN) % H;
    const float* hp = g_hprime + (size_t)row * F_OUT;
    const float* as = a_src + hd * F_OUT;
    const float* ad = a_dst + hd * F_OUT;
    int tid = threadIdx.x;
    float ps = 0.f, pd = 0.f;
    for (int f = tid; f < F_OUT; f += 256) {
        float t = tanhf(hp[f]);
        ps += t * as[f];
        pd += t * ad[f];
    }
    __shared__ float r1[8], r2[8];
    for (int o = 16; o; o >>= 1) {
        ps += __shfl_down_sync(0xffffffffu, ps, o);
        pd += __shfl_down_sync(0xffffffffu, pd, o);
    }
    if ((tid & 31) == 0) { r1[tid >> 5] = ps; r2[tid >> 5] = pd; }
    __syncthreads();
    if (tid == 0) {
        float s = 0.f, d = 0.f;
        for (int t = 0; t < 8; t++) { s += r1[t]; d += r2[t]; }
        g_E[row] = __expf(s);
        g_G[row] = __expf(0.2f * s);
        g_T[row] = __expf(-s);
        g_F[row] = __expf(d);
        g_Hv[row] = __expf(0.2f * d);
    }
}

// -------- kernel 3: row sums of unnormalized attention, scale E/G -----------
__global__ __launch_bounds__(256) void row_stats() {
    int row = blockIdx.x;
    int i = row % NN;
    int bh = row / NN;
    int b = bh / H;
    const unsigned* mrow = g_mask + ((size_t)b * NN + i) * WPR;
    const float* Fv = g_F + (size_t)bh * NN;
    const float* Hv = g_Hv + (size_t)bh * NN;
    float Ei = g_E[row], Gi = g_G[row], Ti = g_T[row];
    int tid = threadIdx.x;
    float sum = 0.f;
    for (int j = tid; j < NN; j += 256) {
        if ((mrow[j >> 5] >> (j & 31)) & 1u) {
            float Fj = Fv[j];
            sum += (Fj >= Ti) ? Ei * Fj : Gi * Hv[j];
        }
    }
    __shared__ float red[8];
    for (int o = 16; o; o >>= 1) sum += __shfl_down_sync(0xffffffffu, sum, o);
    if ((tid & 31) == 0) red[tid >> 5] = sum;
    __syncthreads();
    if (tid == 0) {
        float t0 = 0.f;
        for (int t = 0; t < 8; t++) t0 += red[t];
        float inv = 1.f / t0;
        g_Es[row] = Ei * inv;
        g_Gs[row] = Gi * inv;
    }
}

// ------------- kernel 4: out = P @ h_prime + bias  (1-pass fp16) ------------
#define C_AT (NN / 32)
#define STG_AT 4096   // u32 per stage: A 2048 | B 2048

__global__ __launch_bounds__(256) void attn_gemm_f16(float* __restrict__ out,
                                                     const float* __restrict__ bias) {
    extern __shared__ unsigned sm[];
    __shared__ float sT[128], sEs[128], sGs[128];

    int bh = blockIdx.z, b = bh / H;
    int row0 = blockIdx.y * 128, col0 = blockIdx.x * 128;
    const unsigned* Bm = g_hpT + ((size_t)bh * F_OUT + col0) * (NN / 2);
    const float* Fv = g_F + (size_t)bh * NN;
    const float* Hv = g_Hv + (size_t)bh * NN;

    int tid = threadIdx.x, lane = tid & 31, warp = tid >> 5;
    if (tid < 128) {
        int r = bh * NN + row0 + tid;
        sT[tid] = g_T[r];
        sEs[tid] = g_Es[r];
        sGs[tid] = g_Gs[r];
    }
    __syncthreads();

    int wm = (warp & 1) * 64, wn = (warp >> 1) * 32;
    int mb0 = wm >> 4, nb0 = wn >> 3;
    int jl = tid & 15, iblk = tid >> 4;       // P-gen: jpair column, row block
    int bn = tid >> 1, bk = (tid & 1) * 8;    // B loader: n, kpair base

    float acc[4][4][4];
#pragma unroll
    for (int mi = 0; mi < 4; mi++)
#pragma unroll
        for (int ni = 0; ni < 4; ni++)
#pragma unroll
            for (int r = 0; r < 4; r++) acc[mi][ni][r] = 0.f;

    uint4 pB0, pB1;
#define LOADB(c)                                                       \
    do {                                                               \
        size_t gb = (size_t)bn * (NN / 2) + (c) * 16 + bk;             \
        pB0 = *(const uint4*)&Bm[gb]; pB1 = *(const uint4*)&Bm[gb + 4];\
    } while (0)
#define GENP(st, c)                                                                 \
    do {                                                                            \
        int j = (c) * 32 + 2 * jl;                                                  \
        float Fj0 = Fv[j], Fj1 = Fv[j + 1];                                         \
        float Hj0 = Hv[j], Hj1 = Hv[j + 1];                                         \
        const unsigned* mT = g_maskT + ((size_t)b * WPR + (j >> 5)) * NN            \
                             + row0 + iblk * 8;                                     \
        int bitp = j & 31;                                                          \
        _Pragma("unroll")                                                           \
        for (int rr = 0; rr < 8; rr++) {                                            \
            int i = iblk * 8 + rr;                                                  \
            unsigned m = mT[rr];                                                    \
            float p0 = 0.f, p1 = 0.f;                                               \
            if ((m >> bitp) & 1u)                                                   \
                p0 = (Fj0 >= sT[i]) ? sEs[i] * Fj0 : sGs[i] * Hj0;                  \
            if ((m >> (bitp + 1)) & 1u)                                             \
                p1 = (Fj1 >= sT[i]) ? sEs[i] * Fj1 : sGs[i] * Hj1;                  \
            int tt = (i & 7) >> 1;                                                  \
            int X = ((((i >> 4) * 2 + (jl >> 3)) * 32 + (i & 7) * 4) << 2)          \
                    + ((i >> 3) & 1) + (((jl >> 2) & 1) << 1);                      \
            (st)[X + (((jl & 3) ^ tt) << 2)] = h2pack(p0, p1);                      \
        }                                                                           \
    } while (0)

    LOADB(0);
    GENP(sm, 0);
    scatterBT(sm + 2048, bk, bn, pB0);
    scatterBT(sm + 2048, bk + 4, bn, pB1);
    __syncthreads();

    for (int c = 0; c < C_AT; c++) {
        unsigned* st = sm + (c & 1) * STG_AT;
        if (c + 1 < C_AT) LOADB(c + 1);
#pragma unroll
        for (int kk = 0; kk < 2; kk++) {
            unsigned a_f[4][4], b_f[4][2];
#pragma unroll
            for (int mi = 0; mi < 4; mi++) {
                uint4 v = fragA(st, mb0 + mi, kk, lane);
                a_f[mi][0] = v.x; a_f[mi][1] = v.y; a_f[mi][2] = v.z; a_f[mi][3] = v.w;
            }
#pragma unroll
            for (int ni = 0; ni < 4; ni++) {
                uint2 v = fragB(st + 2048, nb0 + ni, kk, lane);
                b_f[ni][0] = v.x; b_f[ni][1] = v.y;
            }
#pragma unroll
            for (int mi = 0; mi < 4; mi++)
#pragma unroll
                for (int ni = 0; ni < 4; ni++)
                    mma_f16(acc[mi][ni], a_f[mi], b_f[ni]);
        }
        if (c + 1 < C_AT) {
            unsigned* st2 = sm + ((c + 1) & 1) * STG_AT;
            GENP(st2, c + 1);
            scatterBT(st2 + 2048, bk, bn, pB0);
            scatterBT(st2 + 2048, bk + 4, bn, pB1);
        }
        __syncthreads();
    }
#undef LOADB
#undef GENP

#pragma unroll
    for (int mi = 0; mi < 4; mi++)
#pragma unroll
        for (int ni = 0; ni < 4; ni++) {
            int r = row0 + wm + mi * 16 + (lane >> 2);
            int cc = col0 + wn + ni * 8 + 2 * (lane & 3);
            float b0 = bias[cc], b1 = bias[cc + 1];
            size_t p0 = ((size_t)bh * NN + r) * F_OUT + cc;
            size_t p1 = ((size_t)bh * NN + r + 8) * F_OUT + cc;
            *(float2*)&out[p0] = make_float2(acc[mi][ni][0] + b0, acc[mi][ni][1] + b1);
            *(float2*)&out[p1] = make_float2(acc[mi][ni][2] + b0, acc[mi][ni][3] + b1);
        }
}

// ---------------------------------------------------------------------------
extern "C" void kernel_launch(void* const* d_in, const int* in_sizes, int n_in,
                              void* d_out, int out_size) {
    const float* hmat = 0; const void* adj = 0; const float* wmat = 0;
    const float* a_src = 0; const float* a_dst = 0; const float* bias = 0;
    for (int i = 0; i < n_in; i++) {
        long sz = in_sizes[i];
        if (sz == (long)BS * NN * F_IN)        hmat = (const float*)d_in[i];
        else if (sz == (long)BS * NN * NN)     adj  = d_in[i];
        else if (sz == (long)H * F_IN * F_OUT) wmat = (const float*)d_in[i];
        else if (sz == (long)H * F_OUT) {
            if (!a_src) a_src = (const float*)d_in[i];
            else        a_dst = (const float*)d_in[i];
        }
        else if (sz == (long)F_OUT)            bias = (const float*)d_in[i];
    }
    float* out = (float*)d_out;

    static int attr_done = 0;
    if (!attr_done) {
        cudaFuncSetAttribute(hp_gemm_f16, cudaFuncAttributeMaxDynamicSharedMemorySize,
                             2 * STG_HP * 4);
        cudaFuncSetAttribute(attn_gemm_f16, cudaFuncAttributeMaxDynamicSharedMemorySize,
                             2 * STG_AT * 4);
        attr_done = 1;
    }

    detect_adj<<<1, 32>>>((const unsigned*)adj);
    pack_adj<<<(BS * NN * WPR + 255) / 256, 256>>>(adj);

    int nh4 = BS * NN * F_IN / 4;
    split_h16<<<(nh4 + 255) / 256, 256>>>((const float4*)hmat, nh4);

    unsigned *wth, *wtl, *hpt;
    float* hpf;
    cudaGetSymbolAddress((void**)&wth, g_wT_hi);
    cudaGetSymbolAddress((void**)&wtl, g_wT_lo);
    cudaGetSymbolAddress((void**)&hpt, g_hpT);
    cudaGetSymbolAddress((void**)&hpf, g_hprime);

    // wT: [hd][k][n] -> [hd][n][kpair] f16 hi/lo
    tsp16<<<dim3(F_OUT / 32, F_IN / 32, H), 256>>>(wmat, wth, wtl, F_IN, F_OUT);

    dim3 gGemm(F_OUT / 128, NN / 128, BS * H);  // (6, 16, 8)
    hp_gemm_f16<<<gGemm, 256, 2 * STG_HP * 4>>>();
    row_dots<<<BS * H * NN, 256>>>(a_src, a_dst);
    row_stats<<<BS * H * NN, 256>>>();
    // hpT: [bh][j][n] -> [bh][n][jpair] f16
    tsp16<<<dim3(F_OUT / 32, NN / 32, BS * H), 256>>>(hpf, hpt, (unsigned*)0, NN, F_OUT);
    attn_gemm_f16<<<gGemm, 256, 2 * STG_AT * 4>>>(out, bias);
}

// round 9
// speedup vs baseline: 3.0162x; 1.2425x over previous
#include <cuda_runtime.h>
#include <cuda_fp16.h>
#include <stdint.h>
#include <math.h>

#define BS 4
#define NN 2048
#define H 2
#define F_IN 768
#define F_OUT 768
#define WPR 64
#define BHN (BS * H * NN)
#define NTILE (F_OUT / 128)   // 6 column tiles -> dot partial slots

// ----------------------------- device scratch ------------------------------
__device__ unsigned g_h16[BS * NN * F_IN / 2];          // f16x2 pairs along k
__device__ unsigned g_wT[H * F_OUT * F_IN / 2];         // [hd][n][kpair] f16
__device__ unsigned g_hpT[BS * H * F_OUT * NN / 2];     // [bh][n][jpair] f16
__device__ float g_psp[NTILE * BHN], g_pdp[NTILE * BHN];  // dot partials per col-tile
__device__ float g_E[BHN], g_G[BHN], g_T[BHN];
__device__ float g_F[BHN], g_Hv[BHN];
__device__ float g_Es[BHN], g_Gs[BHN];
__device__ unsigned g_mask[BS * NN * WPR];     // [b][i][w]
__device__ unsigned g_maskT[BS * WPR * NN];    // [b][w][i]
__device__ int g_is_i32;

// ------------------------------- helpers ------------------------------------
__device__ __forceinline__ unsigned h2pack(float a, float b) {
    __half2 t = __floats2half2_rn(a, b);
    return *(unsigned*)&t;
}
__device__ __forceinline__ void mma_f16(float* d, const unsigned* a, const unsigned* b) {
    asm volatile(
        "mma.sync.aligned.m16n8k16.row.col.f32.f16.f16.f32 "
        "{%0,%1,%2,%3}, {%4,%5,%6,%7}, {%8,%9}, {%0,%1,%2,%3};"
        : "+f"(d[0]), "+f"(d[1]), "+f"(d[2]), "+f"(d[3])
        : "r"(a[0]), "r"(a[1]), "r"(a[2]), "r"(a[3]), "r"(b[0]), "r"(b[1]));
}

// ---- fragment-permuted smem layout (u32 = f16 k-pair) ----------------------
__device__ __forceinline__ void scatterA(unsigned* s, int r, int c0, uint4 v) {
    int t = (r & 7) >> 1;
    int X = ((((r >> 4) * 2 + (c0 >> 3)) * 32 + (r & 7) * 4) << 2)
            + ((r >> 3) & 1) + (((c0 >> 2) & 1) << 1);
    s[X + ((0 ^ t) << 2)] = v.x;
    s[X + ((1 ^ t) << 2)] = v.y;
    s[X + ((2 ^ t) << 2)] = v.z;
    s[X + ((3 ^ t) << 2)] = v.w;
}
__device__ __forceinline__ void scatterBT(unsigned* s, int kp0, int n, uint4 v) {
    int nblk = n >> 3;
    int cx = (nblk & 7) * 2;
    int reg = (kp0 >> 2) & 1;
    int base = (nblk * 2 + (kp0 >> 3)) * 32 + (n & 7) * 4;
    s[(((base + 0) ^ cx) << 1) + reg] = v.x;
    s[(((base + 1) ^ cx) << 1) + reg] = v.y;
    s[(((base + 2) ^ cx) << 1) + reg] = v.z;
    s[(((base + 3) ^ cx) << 1) + reg] = v.w;
}
__device__ __forceinline__ uint4 fragA(const unsigned* s, int mblk, int kk, int lane) {
    int u = ((mblk * 2 + kk) * 32 + lane) ^ (lane >> 3);
    return *(const uint4*)&s[u << 2];
}
__device__ __forceinline__ uint2 fragB(const unsigned* s, int nblk, int kk, int lane) {
    int u = ((nblk * 2 + kk) * 32 + lane) ^ ((nblk & 7) * 2);
    return *(const uint2*)&s[u << 1];
}

// ----------------------- kernel 0a: adjacency dtype -------------------------
__global__ void detect_adj(const unsigned* __restrict__ adj) {
    if (threadIdx.x == 0 && blockIdx.x == 0) {
        int ok = 1;
        for (int i = 0; i < 64; i++)
            if (adj[i] > 1u) ok = 0;
        g_is_i32 = ok;
    }
}

// ----------------------- kernel 0b: pack adjacency --------------------------
__global__ __launch_bounds__(256) void pack_adj(const void* __restrict__ adjraw) {
    int idx = blockIdx.x * blockDim.x + threadIdx.x;
    if (idx >= BS * NN * WPR) return;
    int w = idx % WPR;
    int i = (idx / WPR) % NN;
    int b = idx / (WPR * NN);
    size_t base = (size_t)(idx / WPR) * NN + (size_t)w * 32;
    unsigned bits = 0;
    if (g_is_i32) {
        const uint4* p = (const uint4*)((const unsigned*)adjraw + base);
#pragma unroll
        for (int q = 0; q < 8; q++) {
            uint4 v = p[q];
            bits |= (unsigned)(v.x != 0) << (4 * q);
            bits |= (unsigned)(v.y != 0) << (4 * q + 1);
            bits |= (unsigned)(v.z != 0) << (4 * q + 2);
            bits |= (unsigned)(v.w != 0) << (4 * q + 3);
        }
    } else {
        const unsigned char* p = (const unsigned char*)adjraw + base;
#pragma unroll
        for (int t = 0; t < 32; t++) bits |= (unsigned)(p[t] != 0) << t;
    }
    if ((i >> 5) == w) bits |= 1u << (i & 31);
    g_mask[idx] = bits;
    g_maskT[((size_t)b * WPR + w) * NN + i] = bits;
}

// ------------------ kernel 0c: h fp32 -> f16 k-pairs ------------------------
__global__ __launch_bounds__(256) void cvt_h16(const float4* __restrict__ src, int n4) {
    int i = blockIdx.x * blockDim.x + threadIdx.x;
    if (i >= n4) return;
    float4 v = src[i];
    ((uint2*)g_h16)[i] = make_uint2(h2pack(v.x, v.y), h2pack(v.z, v.w));
}

// --------- kernel 0d: transpose fp32 [z][R][C] -> f16-pair [z][C][R/2] ------
__global__ __launch_bounds__(256) void tsp16(const float* __restrict__ src,
                                             unsigned* __restrict__ dst,
                                             int R, int C) {
    __shared__ float t[32][33];
    int r0 = blockIdx.y * 32, c0 = blockIdx.x * 32, z = blockIdx.z;
    const float* S = src + ((size_t)z * R + r0) * C + c0;
    int tid = threadIdx.x;
    int cl = tid & 31, rl = tid >> 5;
#pragma unroll
    for (int k = 0; k < 4; k++) t[rl + 8 * k][cl] = S[(size_t)(rl + 8 * k) * C + cl];
    __syncthreads();
    int jj = (tid & 15) * 2, cc = tid >> 4;
#pragma unroll
    for (int k = 0; k < 2; k++) {
        int c = cc + 16 * k;
        size_t e = ((size_t)z * C + c0 + c) * (R / 2) + (r0 + jj) / 2;
        dst[e] = h2pack(t[jj][c], t[jj + 1][c]);
    }
}

// ------------- kernel 1: h_prime GEMM + fused dots + hpT epilogue -----------
// 128x128 CTA, 256 thr = 8 warps (2m x 4n), BK=32, double-buffered, 1-pass f16.
#define C_HP (F_IN / 32)   // 24
#define STG_HP 4096        // u32 per stage: A 2048 | B 2048
#define DYN_HP 34816       // bytes: max(2 stages 32KB, 128x68 u32 restage 34KB)

__global__ __launch_bounds__(256) void hp_gemm_f16(const float* __restrict__ a_src,
                                                   const float* __restrict__ a_dst) {
    extern __shared__ unsigned sm[];
    __shared__ float sred[4][128], sdd[4][128];

    int bh = blockIdx.z, b = bh / H, hd = bh % H;
    int row0 = blockIdx.y * 128, col0 = blockIdx.x * 128;
    const unsigned* A = g_h16 + ((size_t)b * NN + row0) * (F_IN / 2);
    const unsigned* Bm = g_wT + ((size_t)hd * F_OUT + col0) * (F_IN / 2);

    int tid = threadIdx.x, lane = tid & 31, warp = tid >> 5;
    int wm = (warp & 1) * 64, wn = (warp >> 1) * 32;
    int mb0 = wm >> 4, nb0 = wn >> 3;
    int ar = tid >> 1, ac = (tid & 1) * 8;
    int bn = tid >> 1, bk = (tid & 1) * 8;

    float acc[4][4][4];
#pragma unroll
    for (int mi = 0; mi < 4; mi++)
#pragma unroll
        for (int ni = 0; ni < 4; ni++)
#pragma unroll
            for (int r = 0; r < 4; r++) acc[mi][ni][r] = 0.f;

    uint4 pA0, pA1, pB0, pB1;
#define LOADG(c)                                                          \
    do {                                                                  \
        size_t ga = (size_t)ar * (F_IN / 2) + (c) * 16 + ac;              \
        pA0 = *(const uint4*)&A[ga]; pA1 = *(const uint4*)&A[ga + 4];     \
        size_t gb = (size_t)bn * (F_IN / 2) + (c) * 16 + bk;              \
        pB0 = *(const uint4*)&Bm[gb]; pB1 = *(const uint4*)&Bm[gb + 4];   \
    } while (0)
#define SCAT(st)                                                          \
    do {                                                                  \
        scatterA((st), ar, ac, pA0); scatterA((st), ar, ac + 4, pA1);     \
        scatterBT((st) + 2048, bk, bn, pB0);                              \
        scatterBT((st) + 2048, bk + 4, bn, pB1);                          \
    } while (0)

    LOADG(0);
    SCAT(sm);
    __syncthreads();

    for (int c = 0; c < C_HP; c++) {
        unsigned* st = sm + (c & 1) * STG_HP;
        if (c + 1 < C_HP) LOADG(c + 1);
#pragma unroll
        for (int kk = 0; kk < 2; kk++) {
            unsigned a_f[4][4], b_f[4][2];
#pragma unroll
            for (int mi = 0; mi < 4; mi++) {
                uint4 v = fragA(st, mb0 + mi, kk, lane);
                a_f[mi][0] = v.x; a_f[mi][1] = v.y; a_f[mi][2] = v.z; a_f[mi][3] = v.w;
            }
#pragma unroll
            for (int ni = 0; ni < 4; ni++) {
                uint2 v = fragB(st + 2048, nb0 + ni, kk, lane);
                b_f[ni][0] = v.x; b_f[ni][1] = v.y;
            }
#pragma unroll
            for (int mi = 0; mi < 4; mi++)
#pragma unroll
                for (int ni = 0; ni < 4; ni++)
                    mma_f16(acc[mi][ni], a_f[mi], b_f[ni]);
        }
        if (c + 1 < C_HP) SCAT(sm + ((c + 1) & 1) * STG_HP);
        __syncthreads();
    }
#undef LOADG
#undef SCAT

    // ---- fused dot partials: ps = sum_cols tanh(hp)*a_src, pd likewise ----
    const float* sa = a_src + hd * F_OUT;
    const float* da = a_dst + hd * F_OUT;
    float av[4][2], dv[4][2];
#pragma unroll
    for (int ni = 0; ni < 4; ni++)
#pragma unroll
        for (int ch = 0; ch < 2; ch++) {
            int cc = col0 + wn + ni * 8 + 2 * (lane & 3) + ch;
            av[ni][ch] = sa[cc];
            dv[ni][ch] = da[cc];
        }
    int wnid = warp >> 1;
#pragma unroll
    for (int mi = 0; mi < 4; mi++)
#pragma unroll
        for (int rh = 0; rh < 2; rh++) {
            float s = 0.f, d = 0.f;
#pragma unroll
            for (int ni = 0; ni < 4; ni++)
#pragma unroll
                for (int ch = 0; ch < 2; ch++) {
                    float t = tanhf(acc[mi][ni][rh * 2 + ch]);
                    s += t * av[ni][ch];
                    d += t * dv[ni][ch];
                }
            s += __shfl_xor_sync(0xffffffffu, s, 1);
            s += __shfl_xor_sync(0xffffffffu, s, 2);
            d += __shfl_xor_sync(0xffffffffu, d, 1);
            d += __shfl_xor_sync(0xffffffffu, d, 2);
            if ((lane & 3) == 0) {
                int rl = wm + mi * 16 + (lane >> 2) + 8 * rh;
                sred[wnid][rl] = s;
                sdd[wnid][rl] = d;
            }
        }
    __syncthreads();
    if (tid < 128) {
        float s = sred[0][tid] + sred[1][tid] + sred[2][tid] + sred[3][tid];
        float d = sdd[0][tid] + sdd[1][tid] + sdd[2][tid] + sdd[3][tid];
        int row = bh * NN + row0 + tid;
        g_psp[blockIdx.x * BHN + row] = s;
        g_pdp[blockIdx.x * BHN + row] = d;
    }

    // ---- transposed f16 h_prime out: restage via smem u[c][jpair] ----------
    __half* us = (__half*)sm;
#pragma unroll
    for (int mi = 0; mi < 4; mi++)
#pragma unroll
        for (int ni = 0; ni < 4; ni++)
#pragma unroll
            for (int k = 0; k < 4; k++) {
                int rl = wm + mi * 16 + (lane >> 2) + 8 * (k >> 1);
                int cl = wn + ni * 8 + 2 * (lane & 3) + (k & 1);
                us[cl * 136 + rl] = __float2half_rn(acc[mi][ni][k]);
            }
    __syncthreads();
    {
        int n = tid >> 1, seg = tid & 1;
        const uint4* urow = (const uint4*)(sm + n * 68 + seg * 32);
        uint4* dst = (uint4*)(g_hpT + ((size_t)bh * F_OUT + col0 + n) * (NN / 2)
                              + (row0 >> 1) + seg * 32);
#pragma unroll
        for (int q = 0; q < 8; q++) dst[q] = urow[q];
    }
}

// ---------------- kernel 2: exp tables from summed dot partials -------------
__global__ __launch_bounds__(256) void exp_tables() {
    int row = blockIdx.x * blockDim.x + threadIdx.x;
    if (row >= BHN) return;
    float s = 0.f, d = 0.f;
#pragma unroll
    for (int x = 0; x < NTILE; x++) {
        s += g_psp[x * BHN + row];
        d += g_pdp[x * BHN + row];
    }
    g_E[row] = __expf(s);
    g_G[row] = __expf(0.2f * s);
    g_T[row] = __expf(-s);
    g_F[row] = __expf(d);
    g_Hv[row] = __expf(0.2f * d);
}

// -------- kernel 3: row sums of unnormalized attention, scale E/G -----------
__global__ __launch_bounds__(256) void row_stats() {
    int row = blockIdx.x;
    int i = row % NN;
    int bh = row / NN;
    int b = bh / H;
    const unsigned* mrow = g_mask + ((size_t)b * NN + i) * WPR;
    const float* Fv = g_F + (size_t)bh * NN;
    const float* Hv = g_Hv + (size_t)bh * NN;
    float Ei = g_E[row], Gi = g_G[row], Ti = g_T[row];
    int tid = threadIdx.x;
    float sum = 0.f;
    for (int j = tid; j < NN; j += 256) {
        if ((mrow[j >> 5] >> (j & 31)) & 1u) {
            float Fj = Fv[j];
            sum += (Fj >= Ti) ? Ei * Fj : Gi * Hv[j];
        }
    }
    __shared__ float red[8];
    for (int o = 16; o; o >>= 1) sum += __shfl_down_sync(0xffffffffu, sum, o);
    if ((tid & 31) == 0) red[tid >> 5] = sum;
    __syncthreads();
    if (tid == 0) {
        float t0 = 0.f;
        for (int t = 0; t < 8; t++) t0 += red[t];
        float inv = 1.f / t0;
        g_Es[row] = Ei * inv;
        g_Gs[row] = Gi * inv;
    }
}

// ------------- kernel 4: out = P @ h_prime + bias  (1-pass fp16) ------------
#define C_AT (NN / 32)
#define STG_AT 4096   // u32 per stage: A 2048 | B 2048

__global__ __launch_bounds__(256) void attn_gemm_f16(float* __restrict__ out,
                                                     const float* __restrict__ bias) {
    extern __shared__ unsigned sm[];
    __shared__ float sT[128], sEs[128], sGs[128];

    int bh = blockIdx.z, b = bh / H;
    int row0 = blockIdx.y * 128, col0 = blockIdx.x * 128;
    const unsigned* Bm = g_hpT + ((size_t)bh * F_OUT + col0) * (NN / 2);
    const float* Fv = g_F + (size_t)bh * NN;
    const float* Hv = g_Hv + (size_t)bh * NN;

    int tid = threadIdx.x, lane = tid & 31, warp = tid >> 5;
    if (tid < 128) {
        int r = bh * NN + row0 + tid;
        sT[tid] = g_T[r];
        sEs[tid] = g_Es[r];
        sGs[tid] = g_Gs[r];
    }
    __syncthreads();

    int wm = (warp & 1) * 64, wn = (warp >> 1) * 32;
    int mb0 = wm >> 4, nb0 = wn >> 3;
    int jl = tid & 15, iblk = tid >> 4;
    int bn = tid >> 1, bk = (tid & 1) * 8;

    float acc[4][4][4];
#pragma unroll
    for (int mi = 0; mi < 4; mi++)
#pragma unroll
        for (int ni = 0; ni < 4; ni++)
#pragma unroll
            for (int r = 0; r < 4; r++) acc[mi][ni][r] = 0.f;

    uint4 pB0, pB1;
#define LOADB(c)                                                       \
    do {                                                               \
        size_t gb = (size_t)bn * (NN / 2) + (c) * 16 + bk;             \
        pB0 = *(const uint4*)&Bm[gb]; pB1 = *(const uint4*)&Bm[gb + 4];\
    } while (0)
#define GENP(st, c)                                                                 \
    do {                                                                            \
        int j = (c) * 32 + 2 * jl;                                                  \
        float Fj0 = Fv[j], Fj1 = Fv[j + 1];                                         \
        float Hj0 = Hv[j], Hj1 = Hv[j + 1];                                         \
        const unsigned* mT = g_maskT + ((size_t)b * WPR + (j >> 5)) * NN            \
                             + row0 + iblk * 8;                                     \
        int bitp = j & 31;                                                          \
        _Pragma("unroll")                                                           \
        for (int rr = 0; rr < 8; rr++) {                                            \
            int i = iblk * 8 + rr;                                                  \
            unsigned m = mT[rr];                                                    \
            float p0 = 0.f, p1 = 0.f;                                               \
            if ((m >> bitp) & 1u)                                                   \
                p0 = (Fj0 >= sT[i]) ? sEs[i] * Fj0 : sGs[i] * Hj0;                  \
            if ((m >> (bitp + 1)) & 1u)                                             \
                p1 = (Fj1 >= sT[i]) ? sEs[i] * Fj1 : sGs[i] * Hj1;                  \
            int tt = (i & 7) >> 1;                                                  \
            int X = ((((i >> 4) * 2 + (jl >> 3)) * 32 + (i & 7) * 4) << 2)          \
                    + ((i >> 3) & 1) + (((jl >> 2) & 1) << 1);                      \
            (st)[X + (((jl & 3) ^ tt) << 2)] = h2pack(p0, p1);                      \
        }                                                                           \
    } while (0)

    LOADB(0);
    GENP(sm, 0);
    scatterBT(sm + 2048, bk, bn, pB0);
    scatterBT(sm + 2048, bk + 4, bn, pB1);
    __syncthreads();

    for (int c = 0; c < C_AT; c++) {
        unsigned* st = sm + (c & 1) * STG_AT;
        if (c + 1 < C_AT) LOADB(c + 1);
#pragma unroll
        for (int kk = 0; kk < 2; kk++) {
            unsigned a_f[4][4], b_f[4][2];
#pragma unroll
            for (int mi = 0; mi < 4; mi++) {
                uint4 v = fragA(st, mb0 + mi, kk, lane);
                a_f[mi][0] = v.x; a_f[mi][1] = v.y; a_f[mi][2] = v.z; a_f[mi][3] = v.w;
            }
#pragma unroll
            for (int ni = 0; ni < 4; ni++) {
                uint2 v = fragB(st + 2048, nb0 + ni, kk, lane);
                b_f[ni][0] = v.x; b_f[ni][1] = v.y;
            }
#pragma unroll
            for (int mi = 0; mi < 4; mi++)
#pragma unroll
                for (int ni = 0; ni < 4; ni++)
                    mma_f16(acc[mi][ni], a_f[mi], b_f[ni]);
        }
        if (c + 1 < C_AT) {
            unsigned* st2 = sm + ((c + 1) & 1) * STG_AT;
            GENP(st2, c + 1);
            scatterBT(st2 + 2048, bk, bn, pB0);
            scatterBT(st2 + 2048, bk + 4, bn, pB1);
        }
        __syncthreads();
    }
#undef LOADB
#undef GENP

#pragma unroll
    for (int mi = 0; mi < 4; mi++)
#pragma unroll
        for (int ni = 0; ni < 4; ni++) {
            int r = row0 + wm + mi * 16 + (lane >> 2);
            int cc = col0 + wn + ni * 8 + 2 * (lane & 3);
            float b0 = bias[cc], b1 = bias[cc + 1];
            size_t p0 = ((size_t)bh * NN + r) * F_OUT + cc;
            size_t p1 = ((size_t)bh * NN + r + 8) * F_OUT + cc;
            *(float2*)&out[p0] = make_float2(acc[mi][ni][0] + b0, acc[mi][ni][1] + b1);
            *(float2*)&out[p1] = make_float2(acc[mi][ni][2] + b0, acc[mi][ni][3] + b1);
        }
}

// ---------------------------------------------------------------------------
extern "C" void kernel_launch(void* const* d_in, const int* in_sizes, int n_in,
                              void* d_out, int out_size) {
    const float* hmat = 0; const void* adj = 0; const float* wmat = 0;
    const float* a_src = 0; const float* a_dst = 0; const float* bias = 0;
    for (int i = 0; i < n_in; i++) {
        long sz = in_sizes[i];
        if (sz == (long)BS * NN * F_IN)        hmat = (const float*)d_in[i];
        else if (sz == (long)BS * NN * NN)     adj  = d_in[i];
        else if (sz == (long)H * F_IN * F_OUT) wmat = (const float*)d_in[i];
        else if (sz == (long)H * F_OUT) {
            if (!a_src) a_src = (const float*)d_in[i];
            else        a_dst = (const float*)d_in[i];
        }
        else if (sz == (long)F_OUT)            bias = (const float*)d_in[i];
    }
    float* out = (float*)d_out;

    static int attr_done = 0;
    if (!attr_done) {
        cudaFuncSetAttribute(hp_gemm_f16, cudaFuncAttributeMaxDynamicSharedMemorySize,
                             DYN_HP);
        cudaFuncSetAttribute(attn_gemm_f16, cudaFuncAttributeMaxDynamicSharedMemorySize,
                             2 * STG_AT * 4);
        attr_done = 1;
    }

    detect_adj<<<1, 32>>>((const unsigned*)adj);
    pack_adj<<<(BS * NN * WPR + 255) / 256, 256>>>(adj);

    int nh4 = BS * NN * F_IN / 4;
    cvt_h16<<<(nh4 + 255) / 256, 256>>>((const float4*)hmat, nh4);

    unsigned* wt;
    cudaGetSymbolAddress((void**)&wt, g_wT);
    // wT: [hd][k][n] -> [hd][n][kpair] f16
    tsp16<<<dim3(F_OUT / 32, F_IN / 32, H), 256>>>(wmat, wt, F_IN, F_OUT);

    dim3 gGemm(F_OUT / 128, NN / 128, BS * H);  // (6, 16, 8)
    hp_gemm_f16<<<gGemm, 256, DYN_HP>>>(a_src, a_dst);
    exp_tables<<<(BHN + 255) / 256, 256>>>();
    row_stats<<<BHN, 256>>>();
    attn_gemm_f16<<<gGemm, 256, 2 * STG_AT * 4>>>(out, bias);
}